// round 14
// baseline (speedup 1.0000x reference)
#include <cuda_runtime.h>
#include <cuda_fp16.h>
#include <math.h>
#include <stdint.h>

#define N_HOST 20000
#define N_FLOW 200000
#define E_HF   400000
#define E_REL  800000
#define GG     64
#define HH     128
#define FI     97
#define SCAN_BLK 1024

// ---------------- scratch (device globals; no allocation allowed) ----------
__device__ __half g_xflowA[(size_t)N_FLOW * HH];   // ping (fp16 activations)
__device__ __half g_xflowB[(size_t)N_FLOW * HH];   // pong
__device__ __half g_trel  [(size_t)N_FLOW * HH];   // transformed flow (rel), fp16
__device__ __half g_th    [(size_t)N_HOST * HH];   // transformed host (h2f), fp16
__device__ float  g_xhostA[(size_t)N_HOST * HH];
__device__ float  g_xhostB[(size_t)N_HOST * HH];
__device__ float  g_aggh  [(size_t)N_HOST * HH];   // f2h aggregation into hosts

__device__ __half g_WFh[3][HH * 2 * HH]; // per layer fp16: [128][256]=[WoComb|Wr_rel]
__device__ float  g_Wf2hPad[HH * HH];    // pad(Wr0_f2h) 97->128 rows
__device__ float  g_biasF[3][HH];        // br_h2f + br_rel per layer
__device__ float  g_zeroBias[HH];        // zero-initialized device global

// CSR scratch (built once per launch, reused across layers)
__device__ int g_csr_rel[E_REL];
__device__ int g_csr_h2f[E_HF];
__device__ int g_csr_f2h[E_HF];
__device__ int g_off_rel[N_FLOW + 1];
__device__ int g_off_h2f[N_FLOW + 1];
__device__ int g_off_f2h[N_HOST + 1];
__device__ int g_cur_rel[N_FLOW];
__device__ int g_cur_h2f[N_FLOW];
__device__ int g_cur_f2h[N_HOST];
__device__ int g_cnt_rel[N_FLOW];
__device__ int g_cnt_h2f[N_FLOW];
__device__ int g_cnt_f2h[N_HOST];
__device__ int g_bsum[3][256];

__device__ unsigned g_poolEnc[GG * HH];
__device__ float    g_pooled [GG * HH];
__device__ float    g_h1[GG * 64];
__device__ float    g_h2[GG * HH];

// ---------------- small helpers -------------------------------------------
__device__ __forceinline__ unsigned enc_f(float f) {
    unsigned u = __float_as_uint(f);
    return (u & 0x80000000u) ? ~u : (u | 0x80000000u);
}
__device__ __forceinline__ float dec_f(unsigned e) {
    return (e & 0x80000000u) ? __uint_as_float(e ^ 0x80000000u)
                             : __uint_as_float(~e);
}
__device__ __forceinline__ uint32_t smaddr(const void* p) {
    return (uint32_t)__cvta_generic_to_shared(p);
}
__device__ __forceinline__ void ldsm4(uint32_t& r0, uint32_t& r1,
                                      uint32_t& r2, uint32_t& r3, uint32_t a) {
    asm volatile("ldmatrix.sync.aligned.m8n8.x4.shared.b16 {%0,%1,%2,%3}, [%4];"
                 : "=r"(r0), "=r"(r1), "=r"(r2), "=r"(r3) : "r"(a));
}
__device__ __forceinline__ void ldsm4t(uint32_t& r0, uint32_t& r1,
                                       uint32_t& r2, uint32_t& r3, uint32_t a) {
    asm volatile("ldmatrix.sync.aligned.m8n8.x4.trans.shared.b16 {%0,%1,%2,%3}, [%4];"
                 : "=r"(r0), "=r"(r1), "=r"(r2), "=r"(r3) : "r"(a));
}
__device__ __forceinline__ void mma_f16(float4& d, const uint32_t* a,
                                        const uint32_t* b) {
    asm volatile(
        "mma.sync.aligned.m16n8k16.row.col.f32.f16.f16.f32 "
        "{%0,%1,%2,%3}, {%4,%5,%6,%7}, {%8,%9}, {%0,%1,%2,%3};"
        : "+f"(d.x), "+f"(d.y), "+f"(d.z), "+f"(d.w)
        : "r"(a[0]), "r"(a[1]), "r"(a[2]), "r"(a[3]), "r"(b[0]), "r"(b[1]));
}

// ---------------- CSR construction -----------------------------------------
__global__ void hist_kernel(const int* __restrict__ dst, int* __restrict__ cnt,
                            int E) {
    int i = blockIdx.x * blockDim.x + threadIdx.x;
    if (i < E) atomicAdd(&cnt[__ldg(dst + i)], 1);
}

__global__ void scanA_kernel(const int* __restrict__ cnt, int* __restrict__ off,
                             int* __restrict__ bsum, int n) {
    __shared__ int sh[SCAN_BLK];
    int tx = threadIdx.x;
    int i = blockIdx.x * SCAN_BLK + tx;
    int v = (i < n) ? cnt[i] : 0;
    sh[tx] = v;
    __syncthreads();
    for (int d = 1; d < SCAN_BLK; d <<= 1) {
        int t = (tx >= d) ? sh[tx - d] : 0;
        __syncthreads();
        sh[tx] += t;
        __syncthreads();
    }
    if (i < n) off[i] = sh[tx] - v;
    if (tx == SCAN_BLK - 1) bsum[blockIdx.x] = sh[tx];
}

__global__ void scanB_kernel(int* __restrict__ bsum, int nb) {
    __shared__ int sh[256];
    int tx = threadIdx.x;
    int v = (tx < nb) ? bsum[tx] : 0;
    sh[tx] = v;
    __syncthreads();
    for (int d = 1; d < 256; d <<= 1) {
        int t = (tx >= d) ? sh[tx - d] : 0;
        __syncthreads();
        sh[tx] += t;
        __syncthreads();
    }
    if (tx < nb) bsum[tx] = sh[tx] - v;
}

__global__ void scanC_kernel(int* __restrict__ off, int* __restrict__ cur,
                             const int* __restrict__ bsum, int n, int E) {
    int i = blockIdx.x * SCAN_BLK + threadIdx.x;
    if (i < n) {
        int o = off[i] + bsum[blockIdx.x];
        off[i] = o;
        cur[i] = o;
    }
    if (i == 0) off[n] = E;
}

__global__ void fill_kernel(const int* __restrict__ src, const int* __restrict__ dst,
                            int* __restrict__ cur, int* __restrict__ csr, int E) {
    int i = blockIdx.x * blockDim.x + threadIdx.x;
    if (i < E) {
        int d = __ldg(dst + i);
        int p = atomicAdd(&cur[d], 1);
        csr[p] = __ldg(src + i);
    }
}

// ---------------- gathers (R11 layout + index prefetch) ---------------------
__global__ void gather_flow_kernel(const __half* __restrict__ trel,
                                   const __half* __restrict__ th,
                                   const int* __restrict__ off_rel,
                                   const int* __restrict__ csr_rel,
                                   const int* __restrict__ off_h2f,
                                   const int* __restrict__ csr_h2f,
                                   __half* __restrict__ fb) {
    int w = (blockIdx.x * blockDim.x + threadIdx.x) >> 5;
    int lane = threadIdx.x & 31;
    if (w >= N_FLOW) return;
    uint2* fp = (uint2*)(fb + (size_t)w * HH);
    uint2 fv = fp[lane];
    float2 a0 = __half22float2(*(__half2*)&fv.x);
    float2 a1 = __half22float2(*(__half2*)&fv.y);
    float4 acc = make_float4(a0.x, a0.y, a1.x, a1.y);

    int b = __ldg(off_rel + w), e = __ldg(off_rel + w + 1);
    int s = (b < e) ? __ldg(csr_rel + b) : 0;
    for (int i = b; i < e; ++i) {
        int sn = (i + 1 < e) ? __ldg(csr_rel + i + 1) : 0;
        uint2 v = ((const uint2*)(trel + (size_t)s * HH))[lane];
        float2 p0 = __half22float2(*(__half2*)&v.x);
        float2 p1 = __half22float2(*(__half2*)&v.y);
        acc.x += p0.x; acc.y += p0.y; acc.z += p1.x; acc.w += p1.y;
        s = sn;
    }
    b = __ldg(off_h2f + w); e = __ldg(off_h2f + w + 1);
    s = (b < e) ? __ldg(csr_h2f + b) : 0;
    for (int i = b; i < e; ++i) {
        int sn = (i + 1 < e) ? __ldg(csr_h2f + i + 1) : 0;
        uint2 v = ((const uint2*)(th + (size_t)s * HH))[lane];
        float2 p0 = __half22float2(*(__half2*)&v.x);
        float2 p1 = __half22float2(*(__half2*)&v.y);
        acc.x += p0.x; acc.y += p0.y; acc.z += p1.x; acc.w += p1.y;
        s = sn;
    }
    __half2 h0 = __floats2half2_rn(acc.x, acc.y);
    __half2 h1 = __floats2half2_rn(acc.z, acc.w);
    uint2 ov;
    ov.x = *(uint32_t*)&h0; ov.y = *(uint32_t*)&h1;
    fp[lane] = ov;
}

__global__ __launch_bounds__(256)
void gather_flow_pool_kernel(const __half* __restrict__ trel,
                             const __half* __restrict__ th,
                             const __half* __restrict__ fmain,
                             const int* __restrict__ off_rel,
                             const int* __restrict__ csr_rel,
                             const int* __restrict__ off_h2f,
                             const int* __restrict__ csr_h2f,
                             const int* __restrict__ batch,
                             unsigned* __restrict__ pe) {
    __shared__ float sm[8][HH];
    __shared__ int sg[8];
    int warp = threadIdx.x >> 5, lane = threadIdx.x & 31;
    int w = blockIdx.x * 8 + warp;
    float4 acc = make_float4(0.f, 0.f, 0.f, 0.f);
    int g = -1;
    if (w < N_FLOW) {
        g = __ldg(batch + w);
        uint2 fv = ((const uint2*)(fmain + (size_t)w * HH))[lane];
        float2 a0 = __half22float2(*(__half2*)&fv.x);
        float2 a1 = __half22float2(*(__half2*)&fv.y);
        acc = make_float4(a0.x, a0.y, a1.x, a1.y);
        int b = __ldg(off_rel + w), e = __ldg(off_rel + w + 1);
        int s = (b < e) ? __ldg(csr_rel + b) : 0;
        for (int i = b; i < e; ++i) {
            int sn = (i + 1 < e) ? __ldg(csr_rel + i + 1) : 0;
            uint2 v = ((const uint2*)(trel + (size_t)s * HH))[lane];
            float2 p0 = __half22float2(*(__half2*)&v.x);
            float2 p1 = __half22float2(*(__half2*)&v.y);
            acc.x += p0.x; acc.y += p0.y; acc.z += p1.x; acc.w += p1.y;
            s = sn;
        }
        b = __ldg(off_h2f + w); e = __ldg(off_h2f + w + 1);
        s = (b < e) ? __ldg(csr_h2f + b) : 0;
        for (int i = b; i < e; ++i) {
            int sn = (i + 1 < e) ? __ldg(csr_h2f + i + 1) : 0;
            uint2 v = ((const uint2*)(th + (size_t)s * HH))[lane];
            float2 p0 = __half22float2(*(__half2*)&v.x);
            float2 p1 = __half22float2(*(__half2*)&v.y);
            acc.x += p0.x; acc.y += p0.y; acc.z += p1.x; acc.w += p1.y;
            s = sn;
        }
    }
    if (lane == 0) sg[warp] = g;
    *(float4*)&sm[warp][lane * 4] = acc;
    __syncthreads();
    if (threadIdx.x < HH) {
        int c = threadIdx.x;
        int cur = sg[0];
        float m = -INFINITY;
#pragma unroll
        for (int r = 0; r < 8; ++r) {
            int gg = sg[r];
            if (gg != cur) {
                if (cur >= 0) atomicMax(&pe[cur * HH + c], enc_f(m));
                cur = gg; m = -INFINITY;
            }
            if (gg >= 0) m = fmaxf(m, sm[r][c]);
        }
        if (cur >= 0) atomicMax(&pe[cur * HH + c], enc_f(m));
    }
}

__global__ void gather_host_kernel(const __half* __restrict__ fa,
                                   const int* __restrict__ off,
                                   const int* __restrict__ csr,
                                   float* __restrict__ ah, int relu_in) {
    int w = (blockIdx.x * blockDim.x + threadIdx.x) >> 5;
    int lane = threadIdx.x & 31;
    if (w >= N_HOST) return;
    float4 acc = make_float4(0.f, 0.f, 0.f, 0.f);
    int b = __ldg(off + w), e = __ldg(off + w + 1);
    int s = (b < e) ? __ldg(csr + b) : 0;
    for (int i = b; i < e; ++i) {
        int sn = (i + 1 < e) ? __ldg(csr + i + 1) : 0;
        uint2 v = ((const uint2*)(fa + (size_t)s * HH))[lane];
        float2 p0 = __half22float2(*(__half2*)&v.x);
        float2 p1 = __half22float2(*(__half2*)&v.y);
        if (relu_in) {
            p0.x = fmaxf(p0.x, 0.f); p0.y = fmaxf(p0.y, 0.f);
            p1.x = fmaxf(p1.x, 0.f); p1.y = fmaxf(p1.y, 0.f);
        }
        acc.x += p0.x; acc.y += p0.y; acc.z += p1.x; acc.w += p1.y;
        s = sn;
    }
    ((float4*)(ah + (size_t)w * HH))[lane] = acc;
}

// ---------------- prep ------------------------------------------------------
__global__ void embed_kernel(const int* __restrict__ ids,
                             const float* __restrict__ table,
                             float* __restrict__ xh) {
    int i = blockIdx.x * blockDim.x + threadIdx.x;
    if (i >= N_HOST * HH) return;
    int row = i >> 7, c = i & 127;
    xh[i] = table[(size_t)__ldg(ids + row) * HH + c];
}

__global__ void pad_flow_kernel(const float* __restrict__ fx,
                                __half* __restrict__ xf) {
    int i = blockIdx.x * blockDim.x + threadIdx.x;
    if (i >= N_FLOW * HH) return;
    int row = i >> 7, c = i & 127;
    xf[i] = __float2half((c < FI) ? fx[(size_t)row * FI + c] : 0.f);
}

__global__ void prep_weights_kernel(const float* __restrict__ Wo0_h2f,
                                    const float* __restrict__ Wo0_rel,
                                    const float* __restrict__ Wr0_rel,
                                    const float* __restrict__ Wr0_f2h,
                                    const float* __restrict__ Wo,
                                    const float* __restrict__ Wr,
                                    const float* __restrict__ br0_h2f,
                                    const float* __restrict__ br0_rel,
                                    const float* __restrict__ br) {
    int k = blockIdx.x;
    int c = threadIdx.x;
    int idx = k * 256 + c;
    if (c < HH) {
        float v = (k < FI) ? (Wo0_h2f[k * HH + c] + Wo0_rel[k * HH + c]) : 0.f;
        g_WFh[0][idx] = __float2half(v);
        g_Wf2hPad[k * HH + c] = (k < FI) ? Wr0_f2h[k * HH + c] : 0.f;
    } else {
        int cc = c - HH;
        g_WFh[0][idx] = __float2half((k < FI) ? Wr0_rel[k * HH + cc] : 0.f);
    }
    for (int l = 0; l < 2; ++l) {
        float v;
        if (c < HH)
            v = Wo[((size_t)l * 3 + 0) * HH * HH + k * HH + c]
              + Wo[((size_t)l * 3 + 2) * HH * HH + k * HH + c];
        else
            v = Wr[((size_t)l * 3 + 2) * HH * HH + k * HH + (c - HH)];
        g_WFh[l + 1][idx] = __float2half(v);
    }
    if (k == 0 && c < HH) {
        g_biasF[0][c] = br0_h2f[c] + br0_rel[c];
        for (int l = 0; l < 2; ++l)
            g_biasF[l + 1][c] = br[(l * 3 + 0) * HH + c] + br[(l * 3 + 2) * HH + c];
        g_zeroBias[c] = 0.f;
    }
}

// ---------------- fp16 HMMA GEMM (flow path) --------------------------------
__global__ __launch_bounds__(512, 1)
void gemm_dual_h_kernel(const __half* __restrict__ A, const __half* __restrict__ W,
                        const float* __restrict__ bias,
                        __half* __restrict__ out_main, __half* __restrict__ out_aux,
                        int M, int relu_in) {
    const int BK = 16;
    __shared__ __half As[2][128][16];
    __shared__ __half Ws[2][BK][264];

    int tid  = threadIdx.x;
    int warp = tid >> 5, lane = tid & 31;
    int wm = warp >> 2, wn = warp & 3;
    int tg = lane & 3, gp = lane >> 2;
    int row0 = blockIdx.x * 128;

    float4 acc[2][8];
#pragma unroll
    for (int i = 0; i < 2; ++i)
#pragma unroll
        for (int j = 0; j < 8; ++j) acc[i][j] = make_float4(0.f, 0.f, 0.f, 0.f);

    int a_r = tid >> 2, a_kq = tid & 3;
    int a_grow = row0 + a_r;
    uint2 aREG, wREG[2];
    const __half2 hz = __float2half2_rn(0.f);

    auto loadA = [&](int k0) {
        aREG = make_uint2(0u, 0u);
        if (a_grow < M)
            aREG = *(const uint2*)(A + (size_t)a_grow * HH + k0 + a_kq * 4);
        if (relu_in) {
            *(__half2*)&aREG.x = __hmax2(*(__half2*)&aREG.x, hz);
            *(__half2*)&aREG.y = __hmax2(*(__half2*)&aREG.y, hz);
        }
    };
    auto loadW = [&](int k0) {
#pragma unroll
        for (int i = 0; i < 2; ++i) {
            int idx = tid + i * 512;
            int kk = idx >> 6, cq = idx & 63;
            wREG[i] = *(const uint2*)(W + (size_t)(k0 + kk) * 256 + cq * 4);
        }
    };
    auto storeTile = [&](int buf) {
        *(uint2*)&As[buf][a_r][a_kq * 4] = aREG;
#pragma unroll
        for (int i = 0; i < 2; ++i) {
            int idx = tid + i * 512;
            int kk = idx >> 6, cq = idx & 63;
            *(uint2*)&Ws[buf][kk][cq * 4] = wREG[i];
        }
    };

    loadA(0); loadW(0);
    storeTile(0);
    __syncthreads();

    const int NITER = HH / BK;  // 8
    for (int iter = 0; iter < NITER; ++iter) {
        int cur = iter & 1;
        if (iter + 1 < NITER) {
            int k0 = (iter + 1) * BK;
            loadA(k0); loadW(k0);
        }
        uint32_t af[2][4];
#pragma unroll
        for (int mi = 0; mi < 2; ++mi) {
            int row = wm * 32 + mi * 16 + (lane & 15);
            int col = (lane >> 4) * 8;
            ldsm4(af[mi][0], af[mi][1], af[mi][2], af[mi][3],
                  smaddr(&As[cur][row][col]));
        }
        uint32_t bf[8][2];
#pragma unroll
        for (int pr = 0; pr < 4; ++pr) {
            int krow = lane & 15;
            int ncol = wn * 64 + pr * 16 + ((lane >> 4) * 8);
            uint32_t b0, b1, b2, b3;
            ldsm4t(b0, b1, b2, b3, smaddr(&Ws[cur][krow][ncol]));
            bf[pr * 2][0] = b0; bf[pr * 2][1] = b1;
            bf[pr * 2 + 1][0] = b2; bf[pr * 2 + 1][1] = b3;
        }
#pragma unroll
        for (int mi = 0; mi < 2; ++mi)
#pragma unroll
            for (int ni = 0; ni < 8; ++ni)
                mma_f16(acc[mi][ni], af[mi], bf[ni]);
        if (iter + 1 < NITER) storeTile(1 - cur);
        __syncthreads();
    }

#pragma unroll
    for (int ni = 0; ni < 8; ++ni) {
        int col = wn * 64 + ni * 8 + tg * 2;
        bool main_half = (col < HH);
        float b0 = 0.f, b1 = 0.f;
        if (main_half) { b0 = __ldg(bias + col); b1 = __ldg(bias + col + 1); }
        int oc = main_half ? col : (col - HH);
        __half* outp = main_half ? out_main : out_aux;
#pragma unroll
        for (int mi = 0; mi < 2; ++mi) {
            int r0 = row0 + wm * 32 + mi * 16 + gp;
            int r1 = r0 + 8;
            float4 d = acc[mi][ni];
            if (r0 < M)
                *(__half2*)(outp + (size_t)r0 * HH + oc) =
                    __floats2half2_rn(d.x + b0, d.y + b1);
            if (r1 < M)
                *(__half2*)(outp + (size_t)r1 * HH + oc) =
                    __floats2half2_rn(d.z + b0, d.w + b1);
        }
    }
}

// ---------------- fp32 GEMM (host path, small) ------------------------------
__global__ __launch_bounds__(256)
void gemm2_kernel(const float* __restrict__ A0, const float* __restrict__ W0,
                  const float* __restrict__ A1, const float* __restrict__ W1,
                  const float* __restrict__ bias, float* __restrict__ out,
                  __half* __restrict__ outh,
                  int M, int nsrc, int relu_mask) {
    const int BM = 128, BK = 16;
    __shared__ float As[BK][BM + 4];
    __shared__ float Ws[BK][128];
    int tid = threadIdx.x;
    int tx = tid & 15, ty = tid >> 4;
    int row0 = blockIdx.x * BM;
    float acc[8][8];
#pragma unroll
    for (int i = 0; i < 8; ++i)
#pragma unroll
        for (int j = 0; j < 8; ++j) acc[i][j] = 0.f;

    const float* Aarr[2] = {A0, A1};
    const float* Warr[2] = {W0, W1};

    for (int s = 0; s < nsrc; ++s) {
        const float* A = Aarr[s];
        const float* W = Warr[s];
        int rl = (relu_mask >> s) & 1;
        for (int k0 = 0; k0 < 128; k0 += BK) {
#pragma unroll
            for (int i = 0; i < 2; ++i) {
                int idx = tid + i * 256;
                int r = idx >> 2, kq = idx & 3;
                int grow = row0 + r;
                float4 v = make_float4(0.f, 0.f, 0.f, 0.f);
                if (grow < M)
                    v = *(const float4*)(A + (size_t)grow * 128 + k0 + kq * 4);
                if (rl) {
                    v.x = fmaxf(v.x, 0.f); v.y = fmaxf(v.y, 0.f);
                    v.z = fmaxf(v.z, 0.f); v.w = fmaxf(v.w, 0.f);
                }
                As[kq * 4 + 0][r] = v.x;
                As[kq * 4 + 1][r] = v.y;
                As[kq * 4 + 2][r] = v.z;
                As[kq * 4 + 3][r] = v.w;
            }
#pragma unroll
            for (int i = 0; i < 2; ++i) {
                int idx = tid + i * 256;
                int kk = idx >> 5, cq = idx & 31;
                *(float4*)&Ws[kk][cq * 4] =
                    *(const float4*)(W + (size_t)(k0 + kk) * 128 + cq * 4);
            }
            __syncthreads();
#pragma unroll
            for (int k = 0; k < BK; ++k) {
                float a[8], b[8];
#pragma unroll
                for (int i = 0; i < 8; i += 4)
                    *(float4*)&a[i] = *(const float4*)&As[k][ty * 8 + i];
#pragma unroll
                for (int j = 0; j < 8; j += 4)
                    *(float4*)&b[j] = *(const float4*)&Ws[k][tx * 8 + j];
#pragma unroll
                for (int i = 0; i < 8; ++i)
#pragma unroll
                    for (int j = 0; j < 8; ++j)
                        acc[i][j] = fmaf(a[i], b[j], acc[i][j]);
            }
            __syncthreads();
        }
    }
#pragma unroll
    for (int i = 0; i < 8; ++i) {
        int r = row0 + ty * 8 + i;
        if (r >= M) break;
        if (outh) {
#pragma unroll
            for (int j = 0; j < 8; j += 2) {
                float v0 = acc[i][j]   + __ldg(bias + tx * 8 + j);
                float v1 = acc[i][j+1] + __ldg(bias + tx * 8 + j + 1);
                *(__half2*)(outh + (size_t)r * 128 + tx * 8 + j) =
                    __floats2half2_rn(v0, v1);
            }
        } else {
#pragma unroll
            for (int j = 0; j < 8; ++j)
                out[(size_t)r * 128 + tx * 8 + j] = acc[i][j] + __ldg(bias + tx * 8 + j);
        }
    }
}

// ---------------- pooling + MLP --------------------------------------------
__global__ void pool_init_kernel(unsigned* __restrict__ pe) {
    int i = blockIdx.x * blockDim.x + threadIdx.x;
    if (i < GG * HH) pe[i] = 0x007FFFFFu;
}

__global__ void pool_decode_kernel(const unsigned* __restrict__ pe,
                                   float* __restrict__ p) {
    int i = blockIdx.x * blockDim.x + threadIdx.x;
    if (i < GG * HH) p[i] = dec_f(pe[i]);
}

__global__ void mlp1_kernel(const float* __restrict__ pooled,
                            const float* __restrict__ Wc1,
                            const float* __restrict__ bc1,
                            float* __restrict__ h1) {
    int t = blockIdx.x * blockDim.x + threadIdx.x;
    if (t >= GG * 64) return;
    int g = t >> 6, c = t & 63;
    float acc = bc1[c];
    for (int k = 0; k < HH; ++k)
        acc = fmaf(pooled[g * HH + k], Wc1[k * 64 + c], acc);
    h1[t] = fmaxf(acc, 0.f);
}

__global__ void mlp2_kernel(const float* __restrict__ h1,
                            const float* __restrict__ Wc2,
                            const float* __restrict__ bc2,
                            float* __restrict__ h2) {
    int t = blockIdx.x * blockDim.x + threadIdx.x;
    if (t >= GG * HH) return;
    int g = t >> 7, c = t & 127;
    float acc = bc2[c];
    for (int k = 0; k < 64; ++k)
        acc = fmaf(h1[g * 64 + k], Wc2[k * HH + c], acc);
    h2[t] = fmaxf(acc, 0.f);
}

__global__ void mlp3_kernel(const float* __restrict__ h2,
                            const float* __restrict__ Wc3,
                            const float* __restrict__ bc3,
                            float* __restrict__ out) {
    int t = blockIdx.x * blockDim.x + threadIdx.x;
    if (t >= GG * 10) return;
    int g = t / 10, c = t % 10;
    float acc = bc3[c];
    for (int k = 0; k < HH; ++k)
        acc = fmaf(h2[g * HH + k], Wc3[k * 10 + c], acc);
    out[t] = acc;
}

// ---------------- host orchestration ---------------------------------------
static void build_csr(cudaStream_t st, const int* src, const int* dst, int E, int n,
                      int* cnt, int* off, int* cur, int* csr, int* bsum) {
    int nb = (n + SCAN_BLK - 1) / SCAN_BLK;
    cudaMemsetAsync(cnt, 0, (size_t)n * sizeof(int), st);
    hist_kernel<<<(E + 255) / 256, 256, 0, st>>>(dst, cnt, E);
    scanA_kernel<<<nb, SCAN_BLK, 0, st>>>(cnt, off, bsum, n);
    scanB_kernel<<<1, 256, 0, st>>>(bsum, nb);
    scanC_kernel<<<nb, SCAN_BLK, 0, st>>>(off, cur, bsum, n, E);
    fill_kernel<<<(E + 255) / 256, 256, 0, st>>>(src, dst, cur, csr, E);
}

extern "C" void kernel_launch(void* const* d_in, const int* in_sizes, int n_in,
                              void* d_out, int out_size) {
    const int*   host_ids  = (const int*)  d_in[0];
    const float* flow_x    = (const float*)d_in[1];
    const int*   h2f_src   = (const int*)  d_in[2];
    const int*   h2f_dst   = (const int*)  d_in[3];
    const int*   f2h_src   = (const int*)  d_in[4];
    const int*   f2h_dst   = (const int*)  d_in[5];
    const int*   rel_src   = (const int*)  d_in[6];
    const int*   rel_dst   = (const int*)  d_in[7];
    const int*   flow_batch= (const int*)  d_in[8];
    const float* host_embed= (const float*)d_in[9];
    const float* Wr0_h2f   = (const float*)d_in[10];
    const float* br0_h2f   = (const float*)d_in[11];
    const float* Wo0_h2f   = (const float*)d_in[12];
    const float* Wr0_f2h   = (const float*)d_in[13];
    const float* br0_f2h   = (const float*)d_in[14];
    const float* Wo0_f2h   = (const float*)d_in[15];
    const float* Wr0_rel   = (const float*)d_in[16];
    const float* br0_rel   = (const float*)d_in[17];
    const float* Wo0_rel   = (const float*)d_in[18];
    const float* Wr        = (const float*)d_in[19];  // [2,3,128,128]
    const float* br        = (const float*)d_in[20];  // [2,3,128]
    const float* Wo        = (const float*)d_in[21];  // [2,3,128,128]
    const float* Wc1       = (const float*)d_in[22];
    const float* bc1       = (const float*)d_in[23];
    const float* Wc2       = (const float*)d_in[24];
    const float* bc2       = (const float*)d_in[25];
    const float* Wc3       = (const float*)d_in[26];
    const float* bc3       = (const float*)d_in[27];
    float* out = (float*)d_out;

    __half *xfA, *xfB, *trel, *th, *WFh;
    float *xhA, *xhB, *ah;
    float *Wf2hPad, *biasF, *zeroBias;
    unsigned* poolEnc; float *pooled, *h1, *h2;
    int *csr_rel, *csr_h2f, *csr_f2h;
    int *off_rel, *off_h2f, *off_f2h;
    int *cur_rel, *cur_h2f, *cur_f2h;
    int *cnt_rel, *cnt_h2f, *cnt_f2h, *bsum;
    cudaGetSymbolAddress((void**)&xfA, g_xflowA);
    cudaGetSymbolAddress((void**)&xfB, g_xflowB);
    cudaGetSymbolAddress((void**)&trel, g_trel);
    cudaGetSymbolAddress((void**)&th,  g_th);
    cudaGetSymbolAddress((void**)&xhA, g_xhostA);
    cudaGetSymbolAddress((void**)&xhB, g_xhostB);
    cudaGetSymbolAddress((void**)&ah,  g_aggh);
    cudaGetSymbolAddress((void**)&WFh, g_WFh);
    cudaGetSymbolAddress((void**)&Wf2hPad, g_Wf2hPad);
    cudaGetSymbolAddress((void**)&biasF,   g_biasF);
    cudaGetSymbolAddress((void**)&zeroBias, g_zeroBias);
    cudaGetSymbolAddress((void**)&poolEnc, g_poolEnc);
    cudaGetSymbolAddress((void**)&pooled,  g_pooled);
    cudaGetSymbolAddress((void**)&h1, g_h1);
    cudaGetSymbolAddress((void**)&h2, g_h2);
    cudaGetSymbolAddress((void**)&csr_rel, g_csr_rel);
    cudaGetSymbolAddress((void**)&csr_h2f, g_csr_h2f);
    cudaGetSymbolAddress((void**)&csr_f2h, g_csr_f2h);
    cudaGetSymbolAddress((void**)&off_rel, g_off_rel);
    cudaGetSymbolAddress((void**)&off_h2f, g_off_h2f);
    cudaGetSymbolAddress((void**)&off_f2h, g_off_f2h);
    cudaGetSymbolAddress((void**)&cur_rel, g_cur_rel);
    cudaGetSymbolAddress((void**)&cur_h2f, g_cur_h2f);
    cudaGetSymbolAddress((void**)&cur_f2h, g_cur_f2h);
    cudaGetSymbolAddress((void**)&cnt_rel, g_cnt_rel);
    cudaGetSymbolAddress((void**)&cnt_h2f, g_cnt_h2f);
    cudaGetSymbolAddress((void**)&cnt_f2h, g_cnt_f2h);
    cudaGetSymbolAddress((void**)&bsum, g_bsum);

    static cudaStream_t sB = nullptr;
    static cudaEvent_t evFork = nullptr, evPrep = nullptr, evCsrB = nullptr,
                       evTh = nullptr, evFlow = nullptr, evHG = nullptr;
    if (!sB) {
        cudaStreamCreateWithFlags(&sB, cudaStreamNonBlocking);
        cudaEventCreateWithFlags(&evFork, cudaEventDisableTiming);
        cudaEventCreateWithFlags(&evPrep, cudaEventDisableTiming);
        cudaEventCreateWithFlags(&evCsrB, cudaEventDisableTiming);
        cudaEventCreateWithFlags(&evTh,   cudaEventDisableTiming);
        cudaEventCreateWithFlags(&evFlow, cudaEventDisableTiming);
        cudaEventCreateWithFlags(&evHG,   cudaEventDisableTiming);
    }
    cudaStream_t s0 = 0;

    int flowBlocks = (N_FLOW + 127) / 128;
    int hostBlocks = (N_HOST + 127) / 128;

    cudaEventRecord(evFork, s0);
    cudaStreamWaitEvent(sB, evFork, 0);

    // s0 prologue: weights + padded fp16 flow features, then GEMM L0
    prep_weights_kernel<<<HH, 256, 0, s0>>>(Wo0_h2f, Wo0_rel, Wr0_rel, Wr0_f2h,
                                            Wo, Wr, br0_h2f, br0_rel, br);
    pad_flow_kernel<<<(N_FLOW * HH + 255) / 256, 256, 0, s0>>>(flow_x, xfA);
    cudaEventRecord(evPrep, s0);

    // sB prologue: embed + pool init + th(L0) + CSR builds + host chain L0
    embed_kernel<<<(N_HOST * HH + 255) / 256, 256, 0, sB>>>(host_ids, host_embed, xhA);
    pool_init_kernel<<<(GG * HH + 255) / 256, 256, 0, sB>>>(poolEnc);
    gemm2_kernel<<<hostBlocks, 256, 0, sB>>>(xhA, Wr0_h2f, nullptr, nullptr,
                                             zeroBias, nullptr, th, N_HOST, 1, 0);
    cudaEventRecord(evTh, sB);
    build_csr(sB, rel_src, rel_dst, E_REL, N_FLOW, cnt_rel, off_rel, cur_rel, csr_rel, bsum + 0 * 256);
    build_csr(sB, h2f_src, h2f_dst, E_HF,  N_FLOW, cnt_h2f, off_h2f, cur_h2f, csr_h2f, bsum + 1 * 256);
    cudaEventRecord(evCsrB, sB);
    build_csr(sB, f2h_src, f2h_dst, E_HF,  N_HOST, cnt_f2h, off_f2h, cur_f2h, csr_f2h, bsum + 2 * 256);
    cudaStreamWaitEvent(sB, evPrep, 0);
    gather_host_kernel<<<(N_HOST * 32 + 255) / 256, 256, 0, sB>>>(
        xfA, off_f2h, csr_f2h, ah, 0);
    cudaEventRecord(evHG, sB);
    gemm2_kernel<<<hostBlocks, 256, 0, sB>>>(ah, Wf2hPad, xhA, Wo0_f2h, br0_f2h,
                                             xhB, nullptr, N_HOST, 2, 0);

    // ---- layer 0 flow (s0) ----
    gemm_dual_h_kernel<<<flowBlocks, 512, 0, s0>>>(xfA, WFh, biasF, xfB, trel, N_FLOW, 0);
    cudaStreamWaitEvent(s0, evTh, 0);
    cudaStreamWaitEvent(s0, evCsrB, 0);
    gather_flow_kernel<<<(N_FLOW * 32 + 255) / 256, 256, 0, s0>>>(
        trel, th, off_rel, csr_rel, off_h2f, csr_h2f, xfB);
    cudaEventRecord(evFlow, s0);

    // ---- layer 1 ----
    {
        const __half* WF1 = WFh + (size_t)1 * HH * 2 * HH;
        const float* bF1 = biasF + (size_t)1 * HH;
        const float* WrH2F = Wr + (size_t)(0 * 3 + 0) * HH * HH;
        const float* WrF2H = Wr + (size_t)(0 * 3 + 1) * HH * HH;
        const float* WoF2H = Wo + (size_t)(0 * 3 + 1) * HH * HH;
        const float* bH    = br + (0 * 3 + 1) * HH;

        cudaStreamWaitEvent(s0, evHG, 0);  // gather_host L0 read xfA
        gemm_dual_h_kernel<<<flowBlocks, 512, 0, s0>>>(xfB, WF1, bF1, xfA, trel, N_FLOW, 1);

        cudaStreamWaitEvent(sB, evFlow, 0);
        gemm2_kernel<<<hostBlocks, 256, 0, sB>>>(xhB, WrH2F, nullptr, nullptr,
                                                 zeroBias, nullptr, th, N_HOST, 1, 1);
        cudaEventRecord(evTh, sB);
        gather_host_kernel<<<(N_HOST * 32 + 255) / 256, 256, 0, sB>>>(
            xfB, off_f2h, csr_f2h, ah, 1);
        cudaEventRecord(evHG, sB);
        gemm2_kernel<<<hostBlocks, 256, 0, sB>>>(ah, WrF2H, xhB, WoF2H, bH,
                                                 xhA, nullptr, N_HOST, 2, 2);

        cudaStreamWaitEvent(s0, evTh, 0);
        gather_flow_kernel<<<(N_FLOW * 32 + 255) / 256, 256, 0, s0>>>(
            trel, th, off_rel, csr_rel, off_h2f, csr_h2f, xfA);
        cudaEventRecord(evFlow, s0);
    }

    // ---- layer 2 (flow only; fused gather+pool) ----
    {
        const __half* WF2 = WFh + (size_t)2 * HH * 2 * HH;
        const float* bF2 = biasF + (size_t)2 * HH;
        const float* WrH2F = Wr + (size_t)(1 * 3 + 0) * HH * HH;

        cudaStreamWaitEvent(s0, evHG, 0);  // gather_host L1 read xfB
        gemm_dual_h_kernel<<<flowBlocks, 512, 0, s0>>>(xfA, WF2, bF2, xfB, trel, N_FLOW, 1);

        cudaStreamWaitEvent(sB, evFlow, 0);
        gemm2_kernel<<<hostBlocks, 256, 0, sB>>>(xhA, WrH2F, nullptr, nullptr,
                                                 zeroBias, nullptr, th, N_HOST, 1, 1);
        cudaEventRecord(evTh, sB);

        cudaStreamWaitEvent(s0, evTh, 0);
        gather_flow_pool_kernel<<<(N_FLOW + 7) / 8, 256, 0, s0>>>(
            trel, th, xfB, off_rel, csr_rel, off_h2f, csr_h2f, flow_batch, poolEnc);
    }

    // epilogue on s0
    pool_decode_kernel<<<(GG * HH + 255) / 256, 256, 0, s0>>>(poolEnc, pooled);
    mlp1_kernel<<<(GG * 64 + 255) / 256, 256, 0, s0>>>(pooled, Wc1, bc1, h1);
    mlp2_kernel<<<(GG * HH + 255) / 256, 256, 0, s0>>>(h1, Wc2, bc2, h2);
    mlp3_kernel<<<(GG * 10 + 255) / 256, 256, 0, s0>>>(h2, Wc3, bc3, out);
}

// round 15
// speedup vs baseline: 1.0733x; 1.0733x over previous
#include <cuda_runtime.h>
#include <cuda_fp16.h>
#include <math.h>
#include <stdint.h>

#define N_HOST 20000
#define N_FLOW 200000
#define E_HF   400000
#define E_REL  800000
#define GG     64
#define HH     128
#define FI     97
#define SCAN_BLK 1024

// ---------------- scratch (device globals; no allocation allowed) ----------
__device__ __half g_xflowA[(size_t)N_FLOW * HH];   // ping (fp16 activations)
__device__ __half g_xflowB[(size_t)N_FLOW * HH];   // pong
__device__ __half g_trel  [(size_t)N_FLOW * HH];   // transformed flow (rel), fp16
__device__ __half g_th    [(size_t)N_HOST * HH];   // transformed host (h2f), fp16
__device__ float  g_xhostA[(size_t)N_HOST * HH];
__device__ float  g_xhostB[(size_t)N_HOST * HH];
__device__ float  g_aggh  [(size_t)N_HOST * HH];   // f2h aggregation into hosts

__device__ __half g_WFh[3][HH * 2 * HH]; // per layer fp16: [128][256]=[WoComb|Wr_rel]
__device__ float  g_Wf2hPad[HH * HH];    // pad(Wr0_f2h) 97->128 rows
__device__ float  g_biasF[3][HH];        // br_h2f + br_rel per layer
__device__ float  g_zeroBias[HH];        // zero-initialized device global

// CSR scratch (built once per launch, reused across layers)
__device__ int g_csr_rel[E_REL];
__device__ int g_csr_h2f[E_HF];
__device__ int g_csr_f2h[E_HF];
__device__ int g_off_rel[N_FLOW + 1];
__device__ int g_off_h2f[N_FLOW + 1];
__device__ int g_off_f2h[N_HOST + 1];
__device__ int g_cur_rel[N_FLOW];
__device__ int g_cur_h2f[N_FLOW];
__device__ int g_cur_f2h[N_HOST];
__device__ int g_cnt_rel[N_FLOW];
__device__ int g_cnt_h2f[N_FLOW];
__device__ int g_cnt_f2h[N_HOST];
__device__ int g_bsum[3][256];

__device__ unsigned g_poolEnc[GG * HH];

// ---------------- small helpers -------------------------------------------
__device__ __forceinline__ unsigned enc_f(float f) {
    unsigned u = __float_as_uint(f);
    return (u & 0x80000000u) ? ~u : (u | 0x80000000u);
}
__device__ __forceinline__ float dec_f(unsigned e) {
    return (e & 0x80000000u) ? __uint_as_float(e ^ 0x80000000u)
                             : __uint_as_float(~e);
}
__device__ __forceinline__ uint32_t smaddr(const void* p) {
    return (uint32_t)__cvta_generic_to_shared(p);
}
__device__ __forceinline__ void ldsm4(uint32_t& r0, uint32_t& r1,
                                      uint32_t& r2, uint32_t& r3, uint32_t a) {
    asm volatile("ldmatrix.sync.aligned.m8n8.x4.shared.b16 {%0,%1,%2,%3}, [%4];"
                 : "=r"(r0), "=r"(r1), "=r"(r2), "=r"(r3) : "r"(a));
}
__device__ __forceinline__ void ldsm4t(uint32_t& r0, uint32_t& r1,
                                       uint32_t& r2, uint32_t& r3, uint32_t a) {
    asm volatile("ldmatrix.sync.aligned.m8n8.x4.trans.shared.b16 {%0,%1,%2,%3}, [%4];"
                 : "=r"(r0), "=r"(r1), "=r"(r2), "=r"(r3) : "r"(a));
}
__device__ __forceinline__ void mma_f16(float4& d, const uint32_t* a,
                                        const uint32_t* b) {
    asm volatile(
        "mma.sync.aligned.m16n8k16.row.col.f32.f16.f16.f32 "
        "{%0,%1,%2,%3}, {%4,%5,%6,%7}, {%8,%9}, {%0,%1,%2,%3};"
        : "+f"(d.x), "+f"(d.y), "+f"(d.z), "+f"(d.w)
        : "r"(a[0]), "r"(a[1]), "r"(a[2]), "r"(a[3]), "r"(b[0]), "r"(b[1]));
}

// ---------------- CSR construction -----------------------------------------
__global__ void hist_kernel(const int* __restrict__ dst, int* __restrict__ cnt,
                            int E) {
    int i = blockIdx.x * blockDim.x + threadIdx.x;
    if (i < E) atomicAdd(&cnt[__ldg(dst + i)], 1);
}

__global__ void scanA_kernel(const int* __restrict__ cnt, int* __restrict__ off,
                             int* __restrict__ bsum, int n) {
    __shared__ int sh[SCAN_BLK];
    int tx = threadIdx.x;
    int i = blockIdx.x * SCAN_BLK + tx;
    int v = (i < n) ? cnt[i] : 0;
    sh[tx] = v;
    __syncthreads();
    for (int d = 1; d < SCAN_BLK; d <<= 1) {
        int t = (tx >= d) ? sh[tx - d] : 0;
        __syncthreads();
        sh[tx] += t;
        __syncthreads();
    }
    if (i < n) off[i] = sh[tx] - v;
    if (tx == SCAN_BLK - 1) bsum[blockIdx.x] = sh[tx];
}

__global__ void scanB_kernel(int* __restrict__ bsum, int nb) {
    __shared__ int sh[256];
    int tx = threadIdx.x;
    int v = (tx < nb) ? bsum[tx] : 0;
    sh[tx] = v;
    __syncthreads();
    for (int d = 1; d < 256; d <<= 1) {
        int t = (tx >= d) ? sh[tx - d] : 0;
        __syncthreads();
        sh[tx] += t;
        __syncthreads();
    }
    if (tx < nb) bsum[tx] = sh[tx] - v;
}

__global__ void scanC_kernel(int* __restrict__ off, int* __restrict__ cur,
                             const int* __restrict__ bsum, int n, int E) {
    int i = blockIdx.x * SCAN_BLK + threadIdx.x;
    if (i < n) {
        int o = off[i] + bsum[blockIdx.x];
        off[i] = o;
        cur[i] = o;
    }
    if (i == 0) off[n] = E;
}

__global__ void fill_kernel(const int* __restrict__ src, const int* __restrict__ dst,
                            int* __restrict__ cur, int* __restrict__ csr, int E) {
    int i = blockIdx.x * blockDim.x + threadIdx.x;
    if (i < E) {
        int d = __ldg(dst + i);
        int p = atomicAdd(&cur[d], 1);
        csr[p] = __ldg(src + i);
    }
}

// ---------------- gathers (R11 known-good) ----------------------------------
__global__ void gather_flow_kernel(const __half* __restrict__ trel,
                                   const __half* __restrict__ th,
                                   const int* __restrict__ off_rel,
                                   const int* __restrict__ csr_rel,
                                   const int* __restrict__ off_h2f,
                                   const int* __restrict__ csr_h2f,
                                   __half* __restrict__ fb) {
    int w = (blockIdx.x * blockDim.x + threadIdx.x) >> 5;
    int lane = threadIdx.x & 31;
    if (w >= N_FLOW) return;
    uint2* fp = (uint2*)(fb + (size_t)w * HH);
    uint2 fv = fp[lane];
    float2 a0 = __half22float2(*(__half2*)&fv.x);
    float2 a1 = __half22float2(*(__half2*)&fv.y);
    float4 acc = make_float4(a0.x, a0.y, a1.x, a1.y);
    int b = __ldg(off_rel + w), e = __ldg(off_rel + w + 1);
    for (int i = b; i < e; ++i) {
        int s = __ldg(csr_rel + i);
        uint2 v = ((const uint2*)(trel + (size_t)s * HH))[lane];
        float2 p0 = __half22float2(*(__half2*)&v.x);
        float2 p1 = __half22float2(*(__half2*)&v.y);
        acc.x += p0.x; acc.y += p0.y; acc.z += p1.x; acc.w += p1.y;
    }
    b = __ldg(off_h2f + w); e = __ldg(off_h2f + w + 1);
    for (int i = b; i < e; ++i) {
        int s = __ldg(csr_h2f + i);
        uint2 v = ((const uint2*)(th + (size_t)s * HH))[lane];
        float2 p0 = __half22float2(*(__half2*)&v.x);
        float2 p1 = __half22float2(*(__half2*)&v.y);
        acc.x += p0.x; acc.y += p0.y; acc.z += p1.x; acc.w += p1.y;
    }
    __half2 h0 = __floats2half2_rn(acc.x, acc.y);
    __half2 h1 = __floats2half2_rn(acc.z, acc.w);
    uint2 ov;
    ov.x = *(uint32_t*)&h0; ov.y = *(uint32_t*)&h1;
    fp[lane] = ov;
}

__global__ __launch_bounds__(256)
void gather_flow_pool_kernel(const __half* __restrict__ trel,
                             const __half* __restrict__ th,
                             const __half* __restrict__ fmain,
                             const int* __restrict__ off_rel,
                             const int* __restrict__ csr_rel,
                             const int* __restrict__ off_h2f,
                             const int* __restrict__ csr_h2f,
                             const int* __restrict__ batch,
                             unsigned* __restrict__ pe) {
    __shared__ float sm[8][HH];
    __shared__ int sg[8];
    int warp = threadIdx.x >> 5, lane = threadIdx.x & 31;
    int w = blockIdx.x * 8 + warp;
    float4 acc = make_float4(0.f, 0.f, 0.f, 0.f);
    int g = -1;
    if (w < N_FLOW) {
        g = __ldg(batch + w);
        uint2 fv = ((const uint2*)(fmain + (size_t)w * HH))[lane];
        float2 a0 = __half22float2(*(__half2*)&fv.x);
        float2 a1 = __half22float2(*(__half2*)&fv.y);
        acc = make_float4(a0.x, a0.y, a1.x, a1.y);
        int b = __ldg(off_rel + w), e = __ldg(off_rel + w + 1);
        for (int i = b; i < e; ++i) {
            int s = __ldg(csr_rel + i);
            uint2 v = ((const uint2*)(trel + (size_t)s * HH))[lane];
            float2 p0 = __half22float2(*(__half2*)&v.x);
            float2 p1 = __half22float2(*(__half2*)&v.y);
            acc.x += p0.x; acc.y += p0.y; acc.z += p1.x; acc.w += p1.y;
        }
        b = __ldg(off_h2f + w); e = __ldg(off_h2f + w + 1);
        for (int i = b; i < e; ++i) {
            int s = __ldg(csr_h2f + i);
            uint2 v = ((const uint2*)(th + (size_t)s * HH))[lane];
            float2 p0 = __half22float2(*(__half2*)&v.x);
            float2 p1 = __half22float2(*(__half2*)&v.y);
            acc.x += p0.x; acc.y += p0.y; acc.z += p1.x; acc.w += p1.y;
        }
    }
    if (lane == 0) sg[warp] = g;
    *(float4*)&sm[warp][lane * 4] = acc;
    __syncthreads();
    if (threadIdx.x < HH) {
        int c = threadIdx.x;
        int cur = sg[0];
        float m = -INFINITY;
#pragma unroll
        for (int r = 0; r < 8; ++r) {
            int gg = sg[r];
            if (gg != cur) {
                if (cur >= 0) atomicMax(&pe[cur * HH + c], enc_f(m));
                cur = gg; m = -INFINITY;
            }
            if (gg >= 0) m = fmaxf(m, sm[r][c]);
        }
        if (cur >= 0) atomicMax(&pe[cur * HH + c], enc_f(m));
    }
}

__global__ void gather_host_kernel(const __half* __restrict__ fa,
                                   const int* __restrict__ off,
                                   const int* __restrict__ csr,
                                   float* __restrict__ ah, int relu_in) {
    int w = (blockIdx.x * blockDim.x + threadIdx.x) >> 5;
    int lane = threadIdx.x & 31;
    if (w >= N_HOST) return;
    float4 acc = make_float4(0.f, 0.f, 0.f, 0.f);
    int b = __ldg(off + w), e = __ldg(off + w + 1);
    for (int i = b; i < e; ++i) {
        int s = __ldg(csr + i);
        uint2 v = ((const uint2*)(fa + (size_t)s * HH))[lane];
        float2 p0 = __half22float2(*(__half2*)&v.x);
        float2 p1 = __half22float2(*(__half2*)&v.y);
        if (relu_in) {
            p0.x = fmaxf(p0.x, 0.f); p0.y = fmaxf(p0.y, 0.f);
            p1.x = fmaxf(p1.x, 0.f); p1.y = fmaxf(p1.y, 0.f);
        }
        acc.x += p0.x; acc.y += p0.y; acc.z += p1.x; acc.w += p1.y;
    }
    ((float4*)(ah + (size_t)w * HH))[lane] = acc;
}

// ---------------- prep ------------------------------------------------------
__global__ void embed_kernel(const int* __restrict__ ids,
                             const float* __restrict__ table,
                             float* __restrict__ xh) {
    int i = blockIdx.x * blockDim.x + threadIdx.x;
    if (i >= N_HOST * HH) return;
    int row = i >> 7, c = i & 127;
    xh[i] = table[(size_t)__ldg(ids + row) * HH + c];
}

__global__ void pad_flow_kernel(const float* __restrict__ fx,
                                __half* __restrict__ xf) {
    int i = blockIdx.x * blockDim.x + threadIdx.x;
    if (i >= N_FLOW * HH) return;
    int row = i >> 7, c = i & 127;
    xf[i] = __float2half((c < FI) ? fx[(size_t)row * FI + c] : 0.f);
}

__global__ void prep_weights_kernel(const float* __restrict__ Wo0_h2f,
                                    const float* __restrict__ Wo0_rel,
                                    const float* __restrict__ Wr0_rel,
                                    const float* __restrict__ Wr0_f2h,
                                    const float* __restrict__ Wo,
                                    const float* __restrict__ Wr,
                                    const float* __restrict__ br0_h2f,
                                    const float* __restrict__ br0_rel,
                                    const float* __restrict__ br) {
    int k = blockIdx.x;
    int c = threadIdx.x;
    int idx = k * 256 + c;
    if (c < HH) {
        float v = (k < FI) ? (Wo0_h2f[k * HH + c] + Wo0_rel[k * HH + c]) : 0.f;
        g_WFh[0][idx] = __float2half(v);
        g_Wf2hPad[k * HH + c] = (k < FI) ? Wr0_f2h[k * HH + c] : 0.f;
    } else {
        int cc = c - HH;
        g_WFh[0][idx] = __float2half((k < FI) ? Wr0_rel[k * HH + cc] : 0.f);
    }
    for (int l = 0; l < 2; ++l) {
        float v;
        if (c < HH)
            v = Wo[((size_t)l * 3 + 0) * HH * HH + k * HH + c]
              + Wo[((size_t)l * 3 + 2) * HH * HH + k * HH + c];
        else
            v = Wr[((size_t)l * 3 + 2) * HH * HH + k * HH + (c - HH)];
        g_WFh[l + 1][idx] = __float2half(v);
    }
    if (k == 0 && c < HH) {
        g_biasF[0][c] = br0_h2f[c] + br0_rel[c];
        for (int l = 0; l < 2; ++l)
            g_biasF[l + 1][c] = br[(l * 3 + 0) * HH + c] + br[(l * 3 + 2) * HH + c];
        g_zeroBias[c] = 0.f;
    }
}

// ---------------- fp16 HMMA GEMM (flow path) --------------------------------
__global__ __launch_bounds__(512, 1)
void gemm_dual_h_kernel(const __half* __restrict__ A, const __half* __restrict__ W,
                        const float* __restrict__ bias,
                        __half* __restrict__ out_main, __half* __restrict__ out_aux,
                        int M, int relu_in) {
    const int BK = 16;
    __shared__ __half As[2][128][16];
    __shared__ __half Ws[2][BK][264];

    int tid  = threadIdx.x;
    int warp = tid >> 5, lane = tid & 31;
    int wm = warp >> 2, wn = warp & 3;
    int tg = lane & 3, gp = lane >> 2;
    int row0 = blockIdx.x * 128;

    float4 acc[2][8];
#pragma unroll
    for (int i = 0; i < 2; ++i)
#pragma unroll
        for (int j = 0; j < 8; ++j) acc[i][j] = make_float4(0.f, 0.f, 0.f, 0.f);

    int a_r = tid >> 2, a_kq = tid & 3;
    int a_grow = row0 + a_r;
    uint2 aREG, wREG[2];
    const __half2 hz = __float2half2_rn(0.f);

    auto loadA = [&](int k0) {
        aREG = make_uint2(0u, 0u);
        if (a_grow < M)
            aREG = *(const uint2*)(A + (size_t)a_grow * HH + k0 + a_kq * 4);
        if (relu_in) {
            *(__half2*)&aREG.x = __hmax2(*(__half2*)&aREG.x, hz);
            *(__half2*)&aREG.y = __hmax2(*(__half2*)&aREG.y, hz);
        }
    };
    auto loadW = [&](int k0) {
#pragma unroll
        for (int i = 0; i < 2; ++i) {
            int idx = tid + i * 512;
            int kk = idx >> 6, cq = idx & 63;
            wREG[i] = *(const uint2*)(W + (size_t)(k0 + kk) * 256 + cq * 4);
        }
    };
    auto storeTile = [&](int buf) {
        *(uint2*)&As[buf][a_r][a_kq * 4] = aREG;
#pragma unroll
        for (int i = 0; i < 2; ++i) {
            int idx = tid + i * 512;
            int kk = idx >> 6, cq = idx & 63;
            *(uint2*)&Ws[buf][kk][cq * 4] = wREG[i];
        }
    };

    loadA(0); loadW(0);
    storeTile(0);
    __syncthreads();

    const int NITER = HH / BK;  // 8
    for (int iter = 0; iter < NITER; ++iter) {
        int cur = iter & 1;
        if (iter + 1 < NITER) {
            int k0 = (iter + 1) * BK;
            loadA(k0); loadW(k0);
        }
        uint32_t af[2][4];
#pragma unroll
        for (int mi = 0; mi < 2; ++mi) {
            int row = wm * 32 + mi * 16 + (lane & 15);
            int col = (lane >> 4) * 8;
            ldsm4(af[mi][0], af[mi][1], af[mi][2], af[mi][3],
                  smaddr(&As[cur][row][col]));
        }
        uint32_t bf[8][2];
#pragma unroll
        for (int pr = 0; pr < 4; ++pr) {
            int krow = lane & 15;
            int ncol = wn * 64 + pr * 16 + ((lane >> 4) * 8);
            uint32_t b0, b1, b2, b3;
            ldsm4t(b0, b1, b2, b3, smaddr(&Ws[cur][krow][ncol]));
            bf[pr * 2][0] = b0; bf[pr * 2][1] = b1;
            bf[pr * 2 + 1][0] = b2; bf[pr * 2 + 1][1] = b3;
        }
#pragma unroll
        for (int mi = 0; mi < 2; ++mi)
#pragma unroll
            for (int ni = 0; ni < 8; ++ni)
                mma_f16(acc[mi][ni], af[mi], bf[ni]);
        if (iter + 1 < NITER) storeTile(1 - cur);
        __syncthreads();
    }

#pragma unroll
    for (int ni = 0; ni < 8; ++ni) {
        int col = wn * 64 + ni * 8 + tg * 2;
        bool main_half = (col < HH);
        float b0 = 0.f, b1 = 0.f;
        if (main_half) { b0 = __ldg(bias + col); b1 = __ldg(bias + col + 1); }
        int oc = main_half ? col : (col - HH);
        __half* outp = main_half ? out_main : out_aux;
#pragma unroll
        for (int mi = 0; mi < 2; ++mi) {
            int r0 = row0 + wm * 32 + mi * 16 + gp;
            int r1 = r0 + 8;
            float4 d = acc[mi][ni];
            if (r0 < M)
                *(__half2*)(outp + (size_t)r0 * HH + oc) =
                    __floats2half2_rn(d.x + b0, d.y + b1);
            if (r1 < M)
                *(__half2*)(outp + (size_t)r1 * HH + oc) =
                    __floats2half2_rn(d.z + b0, d.w + b1);
        }
    }
}

// ---------------- fp32 GEMM (host path, small) ------------------------------
__global__ __launch_bounds__(256)
void gemm2_kernel(const float* __restrict__ A0, const float* __restrict__ W0,
                  const float* __restrict__ A1, const float* __restrict__ W1,
                  const float* __restrict__ bias, float* __restrict__ out,
                  __half* __restrict__ outh,
                  int M, int nsrc, int relu_mask) {
    const int BM = 128, BK = 16;
    __shared__ float As[BK][BM + 4];
    __shared__ float Ws[BK][128];
    int tid = threadIdx.x;
    int tx = tid & 15, ty = tid >> 4;
    int row0 = blockIdx.x * BM;
    float acc[8][8];
#pragma unroll
    for (int i = 0; i < 8; ++i)
#pragma unroll
        for (int j = 0; j < 8; ++j) acc[i][j] = 0.f;

    const float* Aarr[2] = {A0, A1};
    const float* Warr[2] = {W0, W1};

    for (int s = 0; s < nsrc; ++s) {
        const float* A = Aarr[s];
        const float* W = Warr[s];
        int rl = (relu_mask >> s) & 1;
        for (int k0 = 0; k0 < 128; k0 += BK) {
#pragma unroll
            for (int i = 0; i < 2; ++i) {
                int idx = tid + i * 256;
                int r = idx >> 2, kq = idx & 3;
                int grow = row0 + r;
                float4 v = make_float4(0.f, 0.f, 0.f, 0.f);
                if (grow < M)
                    v = *(const float4*)(A + (size_t)grow * 128 + k0 + kq * 4);
                if (rl) {
                    v.x = fmaxf(v.x, 0.f); v.y = fmaxf(v.y, 0.f);
                    v.z = fmaxf(v.z, 0.f); v.w = fmaxf(v.w, 0.f);
                }
                As[kq * 4 + 0][r] = v.x;
                As[kq * 4 + 1][r] = v.y;
                As[kq * 4 + 2][r] = v.z;
                As[kq * 4 + 3][r] = v.w;
            }
#pragma unroll
            for (int i = 0; i < 2; ++i) {
                int idx = tid + i * 256;
                int kk = idx >> 5, cq = idx & 31;
                *(float4*)&Ws[kk][cq * 4] =
                    *(const float4*)(W + (size_t)(k0 + kk) * 128 + cq * 4);
            }
            __syncthreads();
#pragma unroll
            for (int k = 0; k < BK; ++k) {
                float a[8], b[8];
#pragma unroll
                for (int i = 0; i < 8; i += 4)
                    *(float4*)&a[i] = *(const float4*)&As[k][ty * 8 + i];
#pragma unroll
                for (int j = 0; j < 8; j += 4)
                    *(float4*)&b[j] = *(const float4*)&Ws[k][tx * 8 + j];
#pragma unroll
                for (int i = 0; i < 8; ++i)
#pragma unroll
                    for (int j = 0; j < 8; ++j)
                        acc[i][j] = fmaf(a[i], b[j], acc[i][j]);
            }
            __syncthreads();
        }
    }
#pragma unroll
    for (int i = 0; i < 8; ++i) {
        int r = row0 + ty * 8 + i;
        if (r >= M) break;
        if (outh) {
#pragma unroll
            for (int j = 0; j < 8; j += 2) {
                float v0 = acc[i][j]   + __ldg(bias + tx * 8 + j);
                float v1 = acc[i][j+1] + __ldg(bias + tx * 8 + j + 1);
                *(__half2*)(outh + (size_t)r * 128 + tx * 8 + j) =
                    __floats2half2_rn(v0, v1);
            }
        } else {
#pragma unroll
            for (int j = 0; j < 8; ++j)
                out[(size_t)r * 128 + tx * 8 + j] = acc[i][j] + __ldg(bias + tx * 8 + j);
        }
    }
}

// ---------------- pooling + fused classifier --------------------------------
__global__ void pool_init_kernel(unsigned* __restrict__ pe) {
    int i = blockIdx.x * blockDim.x + threadIdx.x;
    if (i < GG * HH) pe[i] = 0x007FFFFFu;
}

// one block per graph (128 threads): decode pooled row -> mlp1 -> mlp2 -> mlp3
__global__ __launch_bounds__(128)
void classifier_kernel(const unsigned* __restrict__ pe,
                       const float* __restrict__ Wc1, const float* __restrict__ bc1,
                       const float* __restrict__ Wc2, const float* __restrict__ bc2,
                       const float* __restrict__ Wc3, const float* __restrict__ bc3,
                       float* __restrict__ out) {
    __shared__ float sp[HH];
    __shared__ float sh1[64];
    __shared__ float sh2[HH];
    int g = blockIdx.x;
    int c = threadIdx.x;

    sp[c] = dec_f(pe[g * HH + c]);
    __syncthreads();

    if (c < 64) {
        float acc = bc1[c];
        for (int k = 0; k < HH; ++k)
            acc = fmaf(sp[k], __ldg(Wc1 + k * 64 + c), acc);
        sh1[c] = fmaxf(acc, 0.f);
    }
    __syncthreads();

    {
        float acc = bc2[c];
        for (int k = 0; k < 64; ++k)
            acc = fmaf(sh1[k], __ldg(Wc2 + k * HH + c), acc);
        sh2[c] = fmaxf(acc, 0.f);
    }
    __syncthreads();

    if (c < 10) {
        float acc = bc3[c];
        for (int k = 0; k < HH; ++k)
            acc = fmaf(sh2[k], __ldg(Wc3 + k * 10 + c), acc);
        out[g * 10 + c] = acc;
    }
}

// ---------------- host orchestration ---------------------------------------
static void build_csr(cudaStream_t st, const int* src, const int* dst, int E, int n,
                      int* cnt, int* off, int* cur, int* csr, int* bsum) {
    int nb = (n + SCAN_BLK - 1) / SCAN_BLK;
    cudaMemsetAsync(cnt, 0, (size_t)n * sizeof(int), st);
    hist_kernel<<<(E + 255) / 256, 256, 0, st>>>(dst, cnt, E);
    scanA_kernel<<<nb, SCAN_BLK, 0, st>>>(cnt, off, bsum, n);
    scanB_kernel<<<1, 256, 0, st>>>(bsum, nb);
    scanC_kernel<<<nb, SCAN_BLK, 0, st>>>(off, cur, bsum, n, E);
    fill_kernel<<<(E + 255) / 256, 256, 0, st>>>(src, dst, cur, csr, E);
}

extern "C" void kernel_launch(void* const* d_in, const int* in_sizes, int n_in,
                              void* d_out, int out_size) {
    const int*   host_ids  = (const int*)  d_in[0];
    const float* flow_x    = (const float*)d_in[1];
    const int*   h2f_src   = (const int*)  d_in[2];
    const int*   h2f_dst   = (const int*)  d_in[3];
    const int*   f2h_src   = (const int*)  d_in[4];
    const int*   f2h_dst   = (const int*)  d_in[5];
    const int*   rel_src   = (const int*)  d_in[6];
    const int*   rel_dst   = (const int*)  d_in[7];
    const int*   flow_batch= (const int*)  d_in[8];
    const float* host_embed= (const float*)d_in[9];
    const float* Wr0_h2f   = (const float*)d_in[10];
    const float* br0_h2f   = (const float*)d_in[11];
    const float* Wo0_h2f   = (const float*)d_in[12];
    const float* Wr0_f2h   = (const float*)d_in[13];
    const float* br0_f2h   = (const float*)d_in[14];
    const float* Wo0_f2h   = (const float*)d_in[15];
    const float* Wr0_rel   = (const float*)d_in[16];
    const float* br0_rel   = (const float*)d_in[17];
    const float* Wo0_rel   = (const float*)d_in[18];
    const float* Wr        = (const float*)d_in[19];  // [2,3,128,128]
    const float* br        = (const float*)d_in[20];  // [2,3,128]
    const float* Wo        = (const float*)d_in[21];  // [2,3,128,128]
    const float* Wc1       = (const float*)d_in[22];
    const float* bc1       = (const float*)d_in[23];
    const float* Wc2       = (const float*)d_in[24];
    const float* bc2       = (const float*)d_in[25];
    const float* Wc3       = (const float*)d_in[26];
    const float* bc3       = (const float*)d_in[27];
    float* out = (float*)d_out;

    __half *xfA, *xfB, *trel, *th, *WFh;
    float *xhA, *xhB, *ah;
    float *Wf2hPad, *biasF, *zeroBias;
    unsigned* poolEnc;
    int *csr_rel, *csr_h2f, *csr_f2h;
    int *off_rel, *off_h2f, *off_f2h;
    int *cur_rel, *cur_h2f, *cur_f2h;
    int *cnt_rel, *cnt_h2f, *cnt_f2h, *bsum;
    cudaGetSymbolAddress((void**)&xfA, g_xflowA);
    cudaGetSymbolAddress((void**)&xfB, g_xflowB);
    cudaGetSymbolAddress((void**)&trel, g_trel);
    cudaGetSymbolAddress((void**)&th,  g_th);
    cudaGetSymbolAddress((void**)&xhA, g_xhostA);
    cudaGetSymbolAddress((void**)&xhB, g_xhostB);
    cudaGetSymbolAddress((void**)&ah,  g_aggh);
    cudaGetSymbolAddress((void**)&WFh, g_WFh);
    cudaGetSymbolAddress((void**)&Wf2hPad, g_Wf2hPad);
    cudaGetSymbolAddress((void**)&biasF,   g_biasF);
    cudaGetSymbolAddress((void**)&zeroBias, g_zeroBias);
    cudaGetSymbolAddress((void**)&poolEnc, g_poolEnc);
    cudaGetSymbolAddress((void**)&csr_rel, g_csr_rel);
    cudaGetSymbolAddress((void**)&csr_h2f, g_csr_h2f);
    cudaGetSymbolAddress((void**)&csr_f2h, g_csr_f2h);
    cudaGetSymbolAddress((void**)&off_rel, g_off_rel);
    cudaGetSymbolAddress((void**)&off_h2f, g_off_h2f);
    cudaGetSymbolAddress((void**)&off_f2h, g_off_f2h);
    cudaGetSymbolAddress((void**)&cur_rel, g_cur_rel);
    cudaGetSymbolAddress((void**)&cur_h2f, g_cur_h2f);
    cudaGetSymbolAddress((void**)&cur_f2h, g_cur_f2h);
    cudaGetSymbolAddress((void**)&cnt_rel, g_cnt_rel);
    cudaGetSymbolAddress((void**)&cnt_h2f, g_cnt_h2f);
    cudaGetSymbolAddress((void**)&cnt_f2h, g_cnt_f2h);
    cudaGetSymbolAddress((void**)&bsum, g_bsum);

    static cudaStream_t sB = nullptr;
    static cudaEvent_t evFork = nullptr, evPrep = nullptr, evCsrB = nullptr,
                       evTh = nullptr, evFlow = nullptr, evHG = nullptr;
    if (!sB) {
        cudaStreamCreateWithFlags(&sB, cudaStreamNonBlocking);
        cudaEventCreateWithFlags(&evFork, cudaEventDisableTiming);
        cudaEventCreateWithFlags(&evPrep, cudaEventDisableTiming);
        cudaEventCreateWithFlags(&evCsrB, cudaEventDisableTiming);
        cudaEventCreateWithFlags(&evTh,   cudaEventDisableTiming);
        cudaEventCreateWithFlags(&evFlow, cudaEventDisableTiming);
        cudaEventCreateWithFlags(&evHG,   cudaEventDisableTiming);
    }
    cudaStream_t s0 = 0;

    int flowBlocks = (N_FLOW + 127) / 128;
    int hostBlocks = (N_HOST + 127) / 128;

    cudaEventRecord(evFork, s0);
    cudaStreamWaitEvent(sB, evFork, 0);

    // s0 prologue: weights + padded fp16 flow features, then GEMM L0
    prep_weights_kernel<<<HH, 256, 0, s0>>>(Wo0_h2f, Wo0_rel, Wr0_rel, Wr0_f2h,
                                            Wo, Wr, br0_h2f, br0_rel, br);
    pad_flow_kernel<<<(N_FLOW * HH + 255) / 256, 256, 0, s0>>>(flow_x, xfA);
    cudaEventRecord(evPrep, s0);

    // sB prologue: embed + pool init + th(L0) + CSR builds + host chain L0
    embed_kernel<<<(N_HOST * HH + 255) / 256, 256, 0, sB>>>(host_ids, host_embed, xhA);
    pool_init_kernel<<<(GG * HH + 255) / 256, 256, 0, sB>>>(poolEnc);
    gemm2_kernel<<<hostBlocks, 256, 0, sB>>>(xhA, Wr0_h2f, nullptr, nullptr,
                                             zeroBias, nullptr, th, N_HOST, 1, 0);
    cudaEventRecord(evTh, sB);
    build_csr(sB, rel_src, rel_dst, E_REL, N_FLOW, cnt_rel, off_rel, cur_rel, csr_rel, bsum + 0 * 256);
    build_csr(sB, h2f_src, h2f_dst, E_HF,  N_FLOW, cnt_h2f, off_h2f, cur_h2f, csr_h2f, bsum + 1 * 256);
    cudaEventRecord(evCsrB, sB);
    build_csr(sB, f2h_src, f2h_dst, E_HF,  N_HOST, cnt_f2h, off_f2h, cur_f2h, csr_f2h, bsum + 2 * 256);
    cudaStreamWaitEvent(sB, evPrep, 0);
    gather_host_kernel<<<(N_HOST * 32 + 255) / 256, 256, 0, sB>>>(
        xfA, off_f2h, csr_f2h, ah, 0);
    cudaEventRecord(evHG, sB);
    gemm2_kernel<<<hostBlocks, 256, 0, sB>>>(ah, Wf2hPad, xhA, Wo0_f2h, br0_f2h,
                                             xhB, nullptr, N_HOST, 2, 0);

    // ---- layer 0 flow (s0) ----
    gemm_dual_h_kernel<<<flowBlocks, 512, 0, s0>>>(xfA, WFh, biasF, xfB, trel, N_FLOW, 0);
    cudaStreamWaitEvent(s0, evTh, 0);
    cudaStreamWaitEvent(s0, evCsrB, 0);
    gather_flow_kernel<<<(N_FLOW * 32 + 255) / 256, 256, 0, s0>>>(
        trel, th, off_rel, csr_rel, off_h2f, csr_h2f, xfB);
    cudaEventRecord(evFlow, s0);

    // ---- layer 1 ----
    {
        const __half* WF1 = WFh + (size_t)1 * HH * 2 * HH;
        const float* bF1 = biasF + (size_t)1 * HH;
        const float* WrH2F = Wr + (size_t)(0 * 3 + 0) * HH * HH;
        const float* WrF2H = Wr + (size_t)(0 * 3 + 1) * HH * HH;
        const float* WoF2H = Wo + (size_t)(0 * 3 + 1) * HH * HH;
        const float* bH    = br + (0 * 3 + 1) * HH;

        cudaStreamWaitEvent(s0, evHG, 0);  // gather_host L0 read xfA
        gemm_dual_h_kernel<<<flowBlocks, 512, 0, s0>>>(xfB, WF1, bF1, xfA, trel, N_FLOW, 1);

        cudaStreamWaitEvent(sB, evFlow, 0);
        gemm2_kernel<<<hostBlocks, 256, 0, sB>>>(xhB, WrH2F, nullptr, nullptr,
                                                 zeroBias, nullptr, th, N_HOST, 1, 1);
        cudaEventRecord(evTh, sB);
        gather_host_kernel<<<(N_HOST * 32 + 255) / 256, 256, 0, sB>>>(
            xfB, off_f2h, csr_f2h, ah, 1);
        cudaEventRecord(evHG, sB);
        gemm2_kernel<<<hostBlocks, 256, 0, sB>>>(ah, WrF2H, xhB, WoF2H, bH,
                                                 xhA, nullptr, N_HOST, 2, 2);

        cudaStreamWaitEvent(s0, evTh, 0);
        gather_flow_kernel<<<(N_FLOW * 32 + 255) / 256, 256, 0, s0>>>(
            trel, th, off_rel, csr_rel, off_h2f, csr_h2f, xfA);
        cudaEventRecord(evFlow, s0);
    }

    // ---- layer 2 (flow only; fused gather+pool) ----
    {
        const __half* WF2 = WFh + (size_t)2 * HH * 2 * HH;
        const float* bF2 = biasF + (size_t)2 * HH;
        const float* WrH2F = Wr + (size_t)(1 * 3 + 0) * HH * HH;

        cudaStreamWaitEvent(s0, evHG, 0);  // gather_host L1 read xfB
        gemm_dual_h_kernel<<<flowBlocks, 512, 0, s0>>>(xfA, WF2, bF2, xfB, trel, N_FLOW, 1);

        cudaStreamWaitEvent(sB, evFlow, 0);
        gemm2_kernel<<<hostBlocks, 256, 0, sB>>>(xhA, WrH2F, nullptr, nullptr,
                                                 zeroBias, nullptr, th, N_HOST, 1, 1);
        cudaEventRecord(evTh, sB);

        cudaStreamWaitEvent(s0, evTh, 0);
        gather_flow_pool_kernel<<<(N_FLOW + 7) / 8, 256, 0, s0>>>(
            trel, th, xfB, off_rel, csr_rel, off_h2f, csr_h2f, flow_batch, poolEnc);
    }

    // fused classifier tail (one launch)
    classifier_kernel<<<GG, 128, 0, s0>>>(poolEnc, Wc1, bc1, Wc2, bc2, Wc3, bc3, out);
}

// round 16
// speedup vs baseline: 1.1070x; 1.0314x over previous
#include <cuda_runtime.h>
#include <cuda_fp16.h>
#include <math.h>
#include <stdint.h>

#define N_HOST 20000
#define N_FLOW 200000
#define E_HF   400000
#define E_REL  800000
#define GG     64
#define HH     128
#define FI     97
#define SCAN_BLK 1024

// ---------------- scratch (device globals; no allocation allowed) ----------
__device__ __half g_xflowA[(size_t)N_FLOW * HH];   // ping (fp16 activations)
__device__ __half g_xflowB[(size_t)N_FLOW * HH];   // pong
__device__ __half g_trel  [(size_t)N_FLOW * HH];   // transformed flow (rel), fp16
__device__ __half g_th    [(size_t)N_HOST * HH];   // transformed host (h2f), fp16
__device__ float  g_xhostA[(size_t)N_HOST * HH];
__device__ float  g_xhostB[(size_t)N_HOST * HH];
__device__ float  g_aggh  [(size_t)N_HOST * HH];   // f2h aggregation into hosts

__device__ __half g_WFh[3][HH * 2 * HH]; // per layer fp16: [128][256]=[WoComb|Wr_rel]
__device__ float  g_Wf2hPad[HH * HH];    // pad(Wr0_f2h) 97->128 rows
__device__ float  g_biasF[3][HH];        // br_h2f + br_rel per layer
__device__ float  g_zeroBias[HH];        // zero-initialized device global

// CSR scratch (built once per launch, reused across layers)
__device__ int g_csr_rel[E_REL];
__device__ int g_csr_h2f[E_HF];
__device__ int g_csr_f2h[E_HF];
__device__ int g_off_rel[N_FLOW + 1];
__device__ int g_off_h2f[N_FLOW + 1];
__device__ int g_off_f2h[N_HOST + 1];
__device__ int g_cur_rel[N_FLOW];
__device__ int g_cur_h2f[N_FLOW];
__device__ int g_cur_f2h[N_HOST];
__device__ int g_cnt_rel[N_FLOW];
__device__ int g_cnt_h2f[N_FLOW];
__device__ int g_cnt_f2h[N_HOST];
__device__ int g_bsum[3][256];

__device__ unsigned g_poolEnc[GG * HH];

// ---------------- small helpers -------------------------------------------
__device__ __forceinline__ unsigned enc_f(float f) {
    unsigned u = __float_as_uint(f);
    return (u & 0x80000000u) ? ~u : (u | 0x80000000u);
}
__device__ __forceinline__ float dec_f(unsigned e) {
    return (e & 0x80000000u) ? __uint_as_float(e ^ 0x80000000u)
                             : __uint_as_float(~e);
}
__device__ __forceinline__ uint32_t smaddr(const void* p) {
    return (uint32_t)__cvta_generic_to_shared(p);
}
__device__ __forceinline__ void ldsm4(uint32_t& r0, uint32_t& r1,
                                      uint32_t& r2, uint32_t& r3, uint32_t a) {
    asm volatile("ldmatrix.sync.aligned.m8n8.x4.shared.b16 {%0,%1,%2,%3}, [%4];"
                 : "=r"(r0), "=r"(r1), "=r"(r2), "=r"(r3) : "r"(a));
}
__device__ __forceinline__ void ldsm4t(uint32_t& r0, uint32_t& r1,
                                       uint32_t& r2, uint32_t& r3, uint32_t a) {
    asm volatile("ldmatrix.sync.aligned.m8n8.x4.trans.shared.b16 {%0,%1,%2,%3}, [%4];"
                 : "=r"(r0), "=r"(r1), "=r"(r2), "=r"(r3) : "r"(a));
}
__device__ __forceinline__ void mma_f16(float4& d, const uint32_t* a,
                                        const uint32_t* b) {
    asm volatile(
        "mma.sync.aligned.m16n8k16.row.col.f32.f16.f16.f32 "
        "{%0,%1,%2,%3}, {%4,%5,%6,%7}, {%8,%9}, {%0,%1,%2,%3};"
        : "+f"(d.x), "+f"(d.y), "+f"(d.z), "+f"(d.w)
        : "r"(a[0]), "r"(a[1]), "r"(a[2]), "r"(a[3]), "r"(b[0]), "r"(b[1]));
}

// ---------------- CSR construction -----------------------------------------
__global__ void hist_kernel(const int* __restrict__ dst, int* __restrict__ cnt,
                            int E) {
    int i = blockIdx.x * blockDim.x + threadIdx.x;
    if (i < E) atomicAdd(&cnt[__ldg(dst + i)], 1);
}

__global__ void scanA_kernel(const int* __restrict__ cnt, int* __restrict__ off,
                             int* __restrict__ bsum, int n) {
    __shared__ int sh[SCAN_BLK];
    int tx = threadIdx.x;
    int i = blockIdx.x * SCAN_BLK + tx;
    int v = (i < n) ? cnt[i] : 0;
    sh[tx] = v;
    __syncthreads();
    for (int d = 1; d < SCAN_BLK; d <<= 1) {
        int t = (tx >= d) ? sh[tx - d] : 0;
        __syncthreads();
        sh[tx] += t;
        __syncthreads();
    }
    if (i < n) off[i] = sh[tx] - v;
    if (tx == SCAN_BLK - 1) bsum[blockIdx.x] = sh[tx];
}

__global__ void scanB_kernel(int* __restrict__ bsum, int nb) {
    __shared__ int sh[256];
    int tx = threadIdx.x;
    int v = (tx < nb) ? bsum[tx] : 0;
    sh[tx] = v;
    __syncthreads();
    for (int d = 1; d < 256; d <<= 1) {
        int t = (tx >= d) ? sh[tx - d] : 0;
        __syncthreads();
        sh[tx] += t;
        __syncthreads();
    }
    if (tx < nb) bsum[tx] = sh[tx] - v;
}

__global__ void scanC_kernel(int* __restrict__ off, int* __restrict__ cur,
                             const int* __restrict__ bsum, int n, int E) {
    int i = blockIdx.x * SCAN_BLK + threadIdx.x;
    if (i < n) {
        int o = off[i] + bsum[blockIdx.x];
        off[i] = o;
        cur[i] = o;
    }
    if (i == 0) off[n] = E;
}

__global__ void fill_kernel(const int* __restrict__ src, const int* __restrict__ dst,
                            int* __restrict__ cur, int* __restrict__ csr, int E) {
    int i = blockIdx.x * blockDim.x + threadIdx.x;
    if (i < E) {
        int d = __ldg(dst + i);
        int p = atomicAdd(&cur[d], 1);
        csr[p] = __ldg(src + i);
    }
}

// ---------------- gathers (R11 known-good) ----------------------------------
__global__ void gather_flow_kernel(const __half* __restrict__ trel,
                                   const __half* __restrict__ th,
                                   const int* __restrict__ off_rel,
                                   const int* __restrict__ csr_rel,
                                   const int* __restrict__ off_h2f,
                                   const int* __restrict__ csr_h2f,
                                   __half* __restrict__ fb) {
    int w = (blockIdx.x * blockDim.x + threadIdx.x) >> 5;
    int lane = threadIdx.x & 31;
    if (w >= N_FLOW) return;
    uint2* fp = (uint2*)(fb + (size_t)w * HH);
    uint2 fv = fp[lane];
    float2 a0 = __half22float2(*(__half2*)&fv.x);
    float2 a1 = __half22float2(*(__half2*)&fv.y);
    float4 acc = make_float4(a0.x, a0.y, a1.x, a1.y);
    int b = __ldg(off_rel + w), e = __ldg(off_rel + w + 1);
    for (int i = b; i < e; ++i) {
        int s = __ldg(csr_rel + i);
        uint2 v = ((const uint2*)(trel + (size_t)s * HH))[lane];
        float2 p0 = __half22float2(*(__half2*)&v.x);
        float2 p1 = __half22float2(*(__half2*)&v.y);
        acc.x += p0.x; acc.y += p0.y; acc.z += p1.x; acc.w += p1.y;
    }
    b = __ldg(off_h2f + w); e = __ldg(off_h2f + w + 1);
    for (int i = b; i < e; ++i) {
        int s = __ldg(csr_h2f + i);
        uint2 v = ((const uint2*)(th + (size_t)s * HH))[lane];
        float2 p0 = __half22float2(*(__half2*)&v.x);
        float2 p1 = __half22float2(*(__half2*)&v.y);
        acc.x += p0.x; acc.y += p0.y; acc.z += p1.x; acc.w += p1.y;
    }
    __half2 h0 = __floats2half2_rn(acc.x, acc.y);
    __half2 h1 = __floats2half2_rn(acc.z, acc.w);
    uint2 ov;
    ov.x = *(uint32_t*)&h0; ov.y = *(uint32_t*)&h1;
    fp[lane] = ov;
}

__global__ __launch_bounds__(256)
void gather_flow_pool_kernel(const __half* __restrict__ trel,
                             const __half* __restrict__ th,
                             const __half* __restrict__ fmain,
                             const int* __restrict__ off_rel,
                             const int* __restrict__ csr_rel,
                             const int* __restrict__ off_h2f,
                             const int* __restrict__ csr_h2f,
                             const int* __restrict__ batch,
                             unsigned* __restrict__ pe) {
    __shared__ float sm[8][HH];
    __shared__ int sg[8];
    int warp = threadIdx.x >> 5, lane = threadIdx.x & 31;
    int w = blockIdx.x * 8 + warp;
    float4 acc = make_float4(0.f, 0.f, 0.f, 0.f);
    int g = -1;
    if (w < N_FLOW) {
        g = __ldg(batch + w);
        uint2 fv = ((const uint2*)(fmain + (size_t)w * HH))[lane];
        float2 a0 = __half22float2(*(__half2*)&fv.x);
        float2 a1 = __half22float2(*(__half2*)&fv.y);
        acc = make_float4(a0.x, a0.y, a1.x, a1.y);
        int b = __ldg(off_rel + w), e = __ldg(off_rel + w + 1);
        for (int i = b; i < e; ++i) {
            int s = __ldg(csr_rel + i);
            uint2 v = ((const uint2*)(trel + (size_t)s * HH))[lane];
            float2 p0 = __half22float2(*(__half2*)&v.x);
            float2 p1 = __half22float2(*(__half2*)&v.y);
            acc.x += p0.x; acc.y += p0.y; acc.z += p1.x; acc.w += p1.y;
        }
        b = __ldg(off_h2f + w); e = __ldg(off_h2f + w + 1);
        for (int i = b; i < e; ++i) {
            int s = __ldg(csr_h2f + i);
            uint2 v = ((const uint2*)(th + (size_t)s * HH))[lane];
            float2 p0 = __half22float2(*(__half2*)&v.x);
            float2 p1 = __half22float2(*(__half2*)&v.y);
            acc.x += p0.x; acc.y += p0.y; acc.z += p1.x; acc.w += p1.y;
        }
    }
    if (lane == 0) sg[warp] = g;
    *(float4*)&sm[warp][lane * 4] = acc;
    __syncthreads();
    if (threadIdx.x < HH) {
        int c = threadIdx.x;
        int cur = sg[0];
        float m = -INFINITY;
#pragma unroll
        for (int r = 0; r < 8; ++r) {
            int gg = sg[r];
            if (gg != cur) {
                if (cur >= 0) atomicMax(&pe[cur * HH + c], enc_f(m));
                cur = gg; m = -INFINITY;
            }
            if (gg >= 0) m = fmaxf(m, sm[r][c]);
        }
        if (cur >= 0) atomicMax(&pe[cur * HH + c], enc_f(m));
    }
}

__global__ void gather_host_kernel(const __half* __restrict__ fa,
                                   const int* __restrict__ off,
                                   const int* __restrict__ csr,
                                   float* __restrict__ ah, int relu_in) {
    int w = (blockIdx.x * blockDim.x + threadIdx.x) >> 5;
    int lane = threadIdx.x & 31;
    if (w >= N_HOST) return;
    float4 acc = make_float4(0.f, 0.f, 0.f, 0.f);
    int b = __ldg(off + w), e = __ldg(off + w + 1);
    for (int i = b; i < e; ++i) {
        int s = __ldg(csr + i);
        uint2 v = ((const uint2*)(fa + (size_t)s * HH))[lane];
        float2 p0 = __half22float2(*(__half2*)&v.x);
        float2 p1 = __half22float2(*(__half2*)&v.y);
        if (relu_in) {
            p0.x = fmaxf(p0.x, 0.f); p0.y = fmaxf(p0.y, 0.f);
            p1.x = fmaxf(p1.x, 0.f); p1.y = fmaxf(p1.y, 0.f);
        }
        acc.x += p0.x; acc.y += p0.y; acc.z += p1.x; acc.w += p1.y;
    }
    ((float4*)(ah + (size_t)w * HH))[lane] = acc;
}

// ---------------- prep ------------------------------------------------------
__global__ void embed_kernel(const int* __restrict__ ids,
                             const float* __restrict__ table,
                             float* __restrict__ xh) {
    int i = blockIdx.x * blockDim.x + threadIdx.x;
    if (i >= N_HOST * HH) return;
    int row = i >> 7, c = i & 127;
    xh[i] = table[(size_t)__ldg(ids + row) * HH + c];
}

__global__ void pad_flow_kernel(const float* __restrict__ fx,
                                __half* __restrict__ xf) {
    int i = blockIdx.x * blockDim.x + threadIdx.x;
    if (i >= N_FLOW * HH) return;
    int row = i >> 7, c = i & 127;
    xf[i] = __float2half((c < FI) ? fx[(size_t)row * FI + c] : 0.f);
}

__global__ void prep_weights_kernel(const float* __restrict__ Wo0_h2f,
                                    const float* __restrict__ Wo0_rel,
                                    const float* __restrict__ Wr0_rel,
                                    const float* __restrict__ Wr0_f2h,
                                    const float* __restrict__ Wo,
                                    const float* __restrict__ Wr,
                                    const float* __restrict__ br0_h2f,
                                    const float* __restrict__ br0_rel,
                                    const float* __restrict__ br) {
    int k = blockIdx.x;
    int c = threadIdx.x;
    int idx = k * 256 + c;
    if (c < HH) {
        float v = (k < FI) ? (Wo0_h2f[k * HH + c] + Wo0_rel[k * HH + c]) : 0.f;
        g_WFh[0][idx] = __float2half(v);
        g_Wf2hPad[k * HH + c] = (k < FI) ? Wr0_f2h[k * HH + c] : 0.f;
    } else {
        int cc = c - HH;
        g_WFh[0][idx] = __float2half((k < FI) ? Wr0_rel[k * HH + cc] : 0.f);
    }
    for (int l = 0; l < 2; ++l) {
        float v;
        if (c < HH)
            v = Wo[((size_t)l * 3 + 0) * HH * HH + k * HH + c]
              + Wo[((size_t)l * 3 + 2) * HH * HH + k * HH + c];
        else
            v = Wr[((size_t)l * 3 + 2) * HH * HH + k * HH + (c - HH)];
        g_WFh[l + 1][idx] = __float2half(v);
    }
    if (k == 0 && c < HH) {
        g_biasF[0][c] = br0_h2f[c] + br0_rel[c];
        for (int l = 0; l < 2; ++l)
            g_biasF[l + 1][c] = br[(l * 3 + 0) * HH + c] + br[(l * 3 + 2) * HH + c];
        g_zeroBias[c] = 0.f;
    }
}

// ---------------- fp16 HMMA GEMM (flow path) --------------------------------
// 64x256 block tile, 256 thr = 8 warps (2M x 4N), warp tile 32x64, BK=16.
__global__ __launch_bounds__(256, 2)
void gemm_dual_h_kernel(const __half* __restrict__ A, const __half* __restrict__ W,
                        const float* __restrict__ bias,
                        __half* __restrict__ out_main, __half* __restrict__ out_aux,
                        int M, int relu_in) {
    const int BK = 16;
    __shared__ __half As[2][64][16];
    __shared__ __half Ws[2][BK][264];

    int tid  = threadIdx.x;
    int warp = tid >> 5, lane = tid & 31;
    int wm = warp >> 2, wn = warp & 3;          // 2 x 4 warp grid
    int tg = lane & 3, gp = lane >> 2;
    int row0 = blockIdx.x * 64;

    float4 acc[2][8];
#pragma unroll
    for (int i = 0; i < 2; ++i)
#pragma unroll
        for (int j = 0; j < 8; ++j) acc[i][j] = make_float4(0.f, 0.f, 0.f, 0.f);

    int a_r = tid >> 2, a_kq = tid & 3;         // 64 rows x 4 quarters
    int a_grow = row0 + a_r;
    uint2 aREG, wREG[4];
    const __half2 hz = __float2half2_rn(0.f);

    auto loadA = [&](int k0) {
        aREG = make_uint2(0u, 0u);
        if (a_grow < M)
            aREG = *(const uint2*)(A + (size_t)a_grow * HH + k0 + a_kq * 4);
        if (relu_in) {
            *(__half2*)&aREG.x = __hmax2(*(__half2*)&aREG.x, hz);
            *(__half2*)&aREG.y = __hmax2(*(__half2*)&aREG.y, hz);
        }
    };
    auto loadW = [&](int k0) {
#pragma unroll
        for (int i = 0; i < 4; ++i) {
            int idx = tid + i * 256;
            int kk = idx >> 6, cq = idx & 63;
            wREG[i] = *(const uint2*)(W + (size_t)(k0 + kk) * 256 + cq * 4);
        }
    };
    auto storeTile = [&](int buf) {
        *(uint2*)&As[buf][a_r][a_kq * 4] = aREG;
#pragma unroll
        for (int i = 0; i < 4; ++i) {
            int idx = tid + i * 256;
            int kk = idx >> 6, cq = idx & 63;
            *(uint2*)&Ws[buf][kk][cq * 4] = wREG[i];
        }
    };

    loadA(0); loadW(0);
    storeTile(0);
    __syncthreads();

    const int NITER = HH / BK;  // 8
    for (int iter = 0; iter < NITER; ++iter) {
        int cur = iter & 1;
        if (iter + 1 < NITER) {
            int k0 = (iter + 1) * BK;
            loadA(k0); loadW(k0);
        }
        uint32_t af[2][4];
#pragma unroll
        for (int mi = 0; mi < 2; ++mi) {
            int row = wm * 32 + mi * 16 + (lane & 15);
            int col = (lane >> 4) * 8;
            ldsm4(af[mi][0], af[mi][1], af[mi][2], af[mi][3],
                  smaddr(&As[cur][row][col]));
        }
        uint32_t bf[8][2];
#pragma unroll
        for (int pr = 0; pr < 4; ++pr) {
            int krow = lane & 15;
            int ncol = wn * 64 + pr * 16 + ((lane >> 4) * 8);
            uint32_t b0, b1, b2, b3;
            ldsm4t(b0, b1, b2, b3, smaddr(&Ws[cur][krow][ncol]));
            bf[pr * 2][0] = b0; bf[pr * 2][1] = b1;
            bf[pr * 2 + 1][0] = b2; bf[pr * 2 + 1][1] = b3;
        }
#pragma unroll
        for (int mi = 0; mi < 2; ++mi)
#pragma unroll
            for (int ni = 0; ni < 8; ++ni)
                mma_f16(acc[mi][ni], af[mi], bf[ni]);
        if (iter + 1 < NITER) storeTile(1 - cur);
        __syncthreads();
    }

#pragma unroll
    for (int ni = 0; ni < 8; ++ni) {
        int col = wn * 64 + ni * 8 + tg * 2;
        bool main_half = (col < HH);
        float b0 = 0.f, b1 = 0.f;
        if (main_half) { b0 = __ldg(bias + col); b1 = __ldg(bias + col + 1); }
        int oc = main_half ? col : (col - HH);
        __half* outp = main_half ? out_main : out_aux;
#pragma unroll
        for (int mi = 0; mi < 2; ++mi) {
            int r0 = row0 + wm * 32 + mi * 16 + gp;
            int r1 = r0 + 8;
            float4 d = acc[mi][ni];
            if (r0 < M)
                *(__half2*)(outp + (size_t)r0 * HH + oc) =
                    __floats2half2_rn(d.x + b0, d.y + b1);
            if (r1 < M)
                *(__half2*)(outp + (size_t)r1 * HH + oc) =
                    __floats2half2_rn(d.z + b0, d.w + b1);
        }
    }
}

// ---------------- fp32 GEMM (host path, small) ------------------------------
__global__ __launch_bounds__(256)
void gemm2_kernel(const float* __restrict__ A0, const float* __restrict__ W0,
                  const float* __restrict__ A1, const float* __restrict__ W1,
                  const float* __restrict__ bias, float* __restrict__ out,
                  __half* __restrict__ outh,
                  int M, int nsrc, int relu_mask) {
    const int BM = 128, BK = 16;
    __shared__ float As[BK][BM + 4];
    __shared__ float Ws[BK][128];
    int tid = threadIdx.x;
    int tx = tid & 15, ty = tid >> 4;
    int row0 = blockIdx.x * BM;
    float acc[8][8];
#pragma unroll
    for (int i = 0; i < 8; ++i)
#pragma unroll
        for (int j = 0; j < 8; ++j) acc[i][j] = 0.f;

    const float* Aarr[2] = {A0, A1};
    const float* Warr[2] = {W0, W1};

    for (int s = 0; s < nsrc; ++s) {
        const float* A = Aarr[s];
        const float* W = Warr[s];
        int rl = (relu_mask >> s) & 1;
        for (int k0 = 0; k0 < 128; k0 += BK) {
#pragma unroll
            for (int i = 0; i < 2; ++i) {
                int idx = tid + i * 256;
                int r = idx >> 2, kq = idx & 3;
                int grow = row0 + r;
                float4 v = make_float4(0.f, 0.f, 0.f, 0.f);
                if (grow < M)
                    v = *(const float4*)(A + (size_t)grow * 128 + k0 + kq * 4);
                if (rl) {
                    v.x = fmaxf(v.x, 0.f); v.y = fmaxf(v.y, 0.f);
                    v.z = fmaxf(v.z, 0.f); v.w = fmaxf(v.w, 0.f);
                }
                As[kq * 4 + 0][r] = v.x;
                As[kq * 4 + 1][r] = v.y;
                As[kq * 4 + 2][r] = v.z;
                As[kq * 4 + 3][r] = v.w;
            }
#pragma unroll
            for (int i = 0; i < 2; ++i) {
                int idx = tid + i * 256;
                int kk = idx >> 5, cq = idx & 31;
                *(float4*)&Ws[kk][cq * 4] =
                    *(const float4*)(W + (size_t)(k0 + kk) * 128 + cq * 4);
            }
            __syncthreads();
#pragma unroll
            for (int k = 0; k < BK; ++k) {
                float a[8], b[8];
#pragma unroll
                for (int i = 0; i < 8; i += 4)
                    *(float4*)&a[i] = *(const float4*)&As[k][ty * 8 + i];
#pragma unroll
                for (int j = 0; j < 8; j += 4)
                    *(float4*)&b[j] = *(const float4*)&Ws[k][tx * 8 + j];
#pragma unroll
                for (int i = 0; i < 8; ++i)
#pragma unroll
                    for (int j = 0; j < 8; ++j)
                        acc[i][j] = fmaf(a[i], b[j], acc[i][j]);
            }
            __syncthreads();
        }
    }
#pragma unroll
    for (int i = 0; i < 8; ++i) {
        int r = row0 + ty * 8 + i;
        if (r >= M) break;
        if (outh) {
#pragma unroll
            for (int j = 0; j < 8; j += 2) {
                float v0 = acc[i][j]   + __ldg(bias + tx * 8 + j);
                float v1 = acc[i][j+1] + __ldg(bias + tx * 8 + j + 1);
                *(__half2*)(outh + (size_t)r * 128 + tx * 8 + j) =
                    __floats2half2_rn(v0, v1);
            }
        } else {
#pragma unroll
            for (int j = 0; j < 8; ++j)
                out[(size_t)r * 128 + tx * 8 + j] = acc[i][j] + __ldg(bias + tx * 8 + j);
        }
    }
}

// ---------------- pooling + fused classifier --------------------------------
__global__ void pool_init_kernel(unsigned* __restrict__ pe) {
    int i = blockIdx.x * blockDim.x + threadIdx.x;
    if (i < GG * HH) pe[i] = 0x007FFFFFu;
}

__global__ __launch_bounds__(128)
void classifier_kernel(const unsigned* __restrict__ pe,
                       const float* __restrict__ Wc1, const float* __restrict__ bc1,
                       const float* __restrict__ Wc2, const float* __restrict__ bc2,
                       const float* __restrict__ Wc3, const float* __restrict__ bc3,
                       float* __restrict__ out) {
    __shared__ float sp[HH];
    __shared__ float sh1[64];
    __shared__ float sh2[HH];
    int g = blockIdx.x;
    int c = threadIdx.x;

    sp[c] = dec_f(pe[g * HH + c]);
    __syncthreads();

    if (c < 64) {
        float acc = bc1[c];
        for (int k = 0; k < HH; ++k)
            acc = fmaf(sp[k], __ldg(Wc1 + k * 64 + c), acc);
        sh1[c] = fmaxf(acc, 0.f);
    }
    __syncthreads();

    {
        float acc = bc2[c];
        for (int k = 0; k < 64; ++k)
            acc = fmaf(sh1[k], __ldg(Wc2 + k * HH + c), acc);
        sh2[c] = fmaxf(acc, 0.f);
    }
    __syncthreads();

    if (c < 10) {
        float acc = bc3[c];
        for (int k = 0; k < HH; ++k)
            acc = fmaf(sh2[k], __ldg(Wc3 + k * 10 + c), acc);
        out[g * 10 + c] = acc;
    }
}

// ---------------- host orchestration ---------------------------------------
static void build_csr(cudaStream_t st, const int* src, const int* dst, int E, int n,
                      int* cnt, int* off, int* cur, int* csr, int* bsum) {
    int nb = (n + SCAN_BLK - 1) / SCAN_BLK;
    cudaMemsetAsync(cnt, 0, (size_t)n * sizeof(int), st);
    hist_kernel<<<(E + 255) / 256, 256, 0, st>>>(dst, cnt, E);
    scanA_kernel<<<nb, SCAN_BLK, 0, st>>>(cnt, off, bsum, n);
    scanB_kernel<<<1, 256, 0, st>>>(bsum, nb);
    scanC_kernel<<<nb, SCAN_BLK, 0, st>>>(off, cur, bsum, n, E);
    fill_kernel<<<(E + 255) / 256, 256, 0, st>>>(src, dst, cur, csr, E);
}

extern "C" void kernel_launch(void* const* d_in, const int* in_sizes, int n_in,
                              void* d_out, int out_size) {
    const int*   host_ids  = (const int*)  d_in[0];
    const float* flow_x    = (const float*)d_in[1];
    const int*   h2f_src   = (const int*)  d_in[2];
    const int*   h2f_dst   = (const int*)  d_in[3];
    const int*   f2h_src   = (const int*)  d_in[4];
    const int*   f2h_dst   = (const int*)  d_in[5];
    const int*   rel_src   = (const int*)  d_in[6];
    const int*   rel_dst   = (const int*)  d_in[7];
    const int*   flow_batch= (const int*)  d_in[8];
    const float* host_embed= (const float*)d_in[9];
    const float* Wr0_h2f   = (const float*)d_in[10];
    const float* br0_h2f   = (const float*)d_in[11];
    const float* Wo0_h2f   = (const float*)d_in[12];
    const float* Wr0_f2h   = (const float*)d_in[13];
    const float* br0_f2h   = (const float*)d_in[14];
    const float* Wo0_f2h   = (const float*)d_in[15];
    const float* Wr0_rel   = (const float*)d_in[16];
    const float* br0_rel   = (const float*)d_in[17];
    const float* Wo0_rel   = (const float*)d_in[18];
    const float* Wr        = (const float*)d_in[19];  // [2,3,128,128]
    const float* br        = (const float*)d_in[20];  // [2,3,128]
    const float* Wo        = (const float*)d_in[21];  // [2,3,128,128]
    const float* Wc1       = (const float*)d_in[22];
    const float* bc1       = (const float*)d_in[23];
    const float* Wc2       = (const float*)d_in[24];
    const float* bc2       = (const float*)d_in[25];
    const float* Wc3       = (const float*)d_in[26];
    const float* bc3       = (const float*)d_in[27];
    float* out = (float*)d_out;

    __half *xfA, *xfB, *trel, *th, *WFh;
    float *xhA, *xhB, *ah;
    float *Wf2hPad, *biasF, *zeroBias;
    unsigned* poolEnc;
    int *csr_rel, *csr_h2f, *csr_f2h;
    int *off_rel, *off_h2f, *off_f2h;
    int *cur_rel, *cur_h2f, *cur_f2h;
    int *cnt_rel, *cnt_h2f, *cnt_f2h, *bsum;
    cudaGetSymbolAddress((void**)&xfA, g_xflowA);
    cudaGetSymbolAddress((void**)&xfB, g_xflowB);
    cudaGetSymbolAddress((void**)&trel, g_trel);
    cudaGetSymbolAddress((void**)&th,  g_th);
    cudaGetSymbolAddress((void**)&xhA, g_xhostA);
    cudaGetSymbolAddress((void**)&xhB, g_xhostB);
    cudaGetSymbolAddress((void**)&ah,  g_aggh);
    cudaGetSymbolAddress((void**)&WFh, g_WFh);
    cudaGetSymbolAddress((void**)&Wf2hPad, g_Wf2hPad);
    cudaGetSymbolAddress((void**)&biasF,   g_biasF);
    cudaGetSymbolAddress((void**)&zeroBias, g_zeroBias);
    cudaGetSymbolAddress((void**)&poolEnc, g_poolEnc);
    cudaGetSymbolAddress((void**)&csr_rel, g_csr_rel);
    cudaGetSymbolAddress((void**)&csr_h2f, g_csr_h2f);
    cudaGetSymbolAddress((void**)&csr_f2h, g_csr_f2h);
    cudaGetSymbolAddress((void**)&off_rel, g_off_rel);
    cudaGetSymbolAddress((void**)&off_h2f, g_off_h2f);
    cudaGetSymbolAddress((void**)&off_f2h, g_off_f2h);
    cudaGetSymbolAddress((void**)&cur_rel, g_cur_rel);
    cudaGetSymbolAddress((void**)&cur_h2f, g_cur_h2f);
    cudaGetSymbolAddress((void**)&cur_f2h, g_cur_f2h);
    cudaGetSymbolAddress((void**)&cnt_rel, g_cnt_rel);
    cudaGetSymbolAddress((void**)&cnt_h2f, g_cnt_h2f);
    cudaGetSymbolAddress((void**)&cnt_f2h, g_cnt_f2h);
    cudaGetSymbolAddress((void**)&bsum, g_bsum);

    static cudaStream_t sB = nullptr;
    static cudaEvent_t evFork = nullptr, evPrep = nullptr, evCsrB = nullptr,
                       evTh = nullptr, evFlow = nullptr, evHG = nullptr;
    if (!sB) {
        cudaStreamCreateWithFlags(&sB, cudaStreamNonBlocking);
        cudaEventCreateWithFlags(&evFork, cudaEventDisableTiming);
        cudaEventCreateWithFlags(&evPrep, cudaEventDisableTiming);
        cudaEventCreateWithFlags(&evCsrB, cudaEventDisableTiming);
        cudaEventCreateWithFlags(&evTh,   cudaEventDisableTiming);
        cudaEventCreateWithFlags(&evFlow, cudaEventDisableTiming);
        cudaEventCreateWithFlags(&evHG,   cudaEventDisableTiming);
    }
    cudaStream_t s0 = 0;

    int flowBlocks = (N_FLOW + 63) / 64;
    int hostBlocks = (N_HOST + 127) / 128;

    cudaEventRecord(evFork, s0);
    cudaStreamWaitEvent(sB, evFork, 0);

    // s0 prologue: weights + padded fp16 flow features, then GEMM L0
    prep_weights_kernel<<<HH, 256, 0, s0>>>(Wo0_h2f, Wo0_rel, Wr0_rel, Wr0_f2h,
                                            Wo, Wr, br0_h2f, br0_rel, br);
    pad_flow_kernel<<<(N_FLOW * HH + 255) / 256, 256, 0, s0>>>(flow_x, xfA);
    cudaEventRecord(evPrep, s0);

    // sB prologue: embed + pool init + th(L0) + CSR builds + host chain L0
    embed_kernel<<<(N_HOST * HH + 255) / 256, 256, 0, sB>>>(host_ids, host_embed, xhA);
    pool_init_kernel<<<(GG * HH + 255) / 256, 256, 0, sB>>>(poolEnc);
    gemm2_kernel<<<hostBlocks, 256, 0, sB>>>(xhA, Wr0_h2f, nullptr, nullptr,
                                             zeroBias, nullptr, th, N_HOST, 1, 0);
    cudaEventRecord(evTh, sB);
    build_csr(sB, rel_src, rel_dst, E_REL, N_FLOW, cnt_rel, off_rel, cur_rel, csr_rel, bsum + 0 * 256);
    build_csr(sB, h2f_src, h2f_dst, E_HF,  N_FLOW, cnt_h2f, off_h2f, cur_h2f, csr_h2f, bsum + 1 * 256);
    cudaEventRecord(evCsrB, sB);
    build_csr(sB, f2h_src, f2h_dst, E_HF,  N_HOST, cnt_f2h, off_f2h, cur_f2h, csr_f2h, bsum + 2 * 256);
    cudaStreamWaitEvent(sB, evPrep, 0);
    gather_host_kernel<<<(N_HOST * 32 + 255) / 256, 256, 0, sB>>>(
        xfA, off_f2h, csr_f2h, ah, 0);
    cudaEventRecord(evHG, sB);
    gemm2_kernel<<<hostBlocks, 256, 0, sB>>>(ah, Wf2hPad, xhA, Wo0_f2h, br0_f2h,
                                             xhB, nullptr, N_HOST, 2, 0);

    // ---- layer 0 flow (s0) ----
    gemm_dual_h_kernel<<<flowBlocks, 256, 0, s0>>>(xfA, WFh, biasF, xfB, trel, N_FLOW, 0);
    cudaStreamWaitEvent(s0, evTh, 0);
    cudaStreamWaitEvent(s0, evCsrB, 0);
    gather_flow_kernel<<<(N_FLOW * 32 + 255) / 256, 256, 0, s0>>>(
        trel, th, off_rel, csr_rel, off_h2f, csr_h2f, xfB);
    cudaEventRecord(evFlow, s0);

    // ---- layer 1 ----
    {
        const __half* WF1 = WFh + (size_t)1 * HH * 2 * HH;
        const float* bF1 = biasF + (size_t)1 * HH;
        const float* WrH2F = Wr + (size_t)(0 * 3 + 0) * HH * HH;
        const float* WrF2H = Wr + (size_t)(0 * 3 + 1) * HH * HH;
        const float* WoF2H = Wo + (size_t)(0 * 3 + 1) * HH * HH;
        const float* bH    = br + (0 * 3 + 1) * HH;

        cudaStreamWaitEvent(s0, evHG, 0);  // gather_host L0 read xfA
        gemm_dual_h_kernel<<<flowBlocks, 256, 0, s0>>>(xfB, WF1, bF1, xfA, trel, N_FLOW, 1);

        cudaStreamWaitEvent(sB, evFlow, 0);
        gemm2_kernel<<<hostBlocks, 256, 0, sB>>>(xhB, WrH2F, nullptr, nullptr,
                                                 zeroBias, nullptr, th, N_HOST, 1, 1);
        cudaEventRecord(evTh, sB);
        gather_host_kernel<<<(N_HOST * 32 + 255) / 256, 256, 0, sB>>>(
            xfB, off_f2h, csr_f2h, ah, 1);
        cudaEventRecord(evHG, sB);
        gemm2_kernel<<<hostBlocks, 256, 0, sB>>>(ah, WrF2H, xhB, WoF2H, bH,
                                                 xhA, nullptr, N_HOST, 2, 2);

        cudaStreamWaitEvent(s0, evTh, 0);
        gather_flow_kernel<<<(N_FLOW * 32 + 255) / 256, 256, 0, s0>>>(
            trel, th, off_rel, csr_rel, off_h2f, csr_h2f, xfA);
        cudaEventRecord(evFlow, s0);
    }

    // ---- layer 2 (flow only; fused gather+pool) ----
    {
        const __half* WF2 = WFh + (size_t)2 * HH * 2 * HH;
        const float* bF2 = biasF + (size_t)2 * HH;
        const float* WrH2F = Wr + (size_t)(1 * 3 + 0) * HH * HH;

        cudaStreamWaitEvent(s0, evHG, 0);  // gather_host L1 read xfB
        gemm_dual_h_kernel<<<flowBlocks, 256, 0, s0>>>(xfA, WF2, bF2, xfB, trel, N_FLOW, 1);

        cudaStreamWaitEvent(sB, evFlow, 0);
        gemm2_kernel<<<hostBlocks, 256, 0, sB>>>(xhA, WrH2F, nullptr, nullptr,
                                                 zeroBias, nullptr, th, N_HOST, 1, 1);
        cudaEventRecord(evTh, sB);

        cudaStreamWaitEvent(s0, evTh, 0);
        gather_flow_pool_kernel<<<(N_FLOW + 7) / 8, 256, 0, s0>>>(
            trel, th, xfB, off_rel, csr_rel, off_h2f, csr_h2f, flow_batch, poolEnc);
    }

    // fused classifier tail (one launch)
    classifier_kernel<<<GG, 128, 0, s0>>>(poolEnc, Wc1, bc1, Wc2, bc2, Wc3, bc3, out);
}

// round 17
// speedup vs baseline: 1.1120x; 1.0045x over previous
#include <cuda_runtime.h>
#include <cuda_fp16.h>
#include <math.h>
#include <stdint.h>

#define N_HOST 20000
#define N_FLOW 200000
#define E_HF   400000
#define E_REL  800000
#define GG     64
#define HH     128
#define FI     97
#define SCAN_BLK 1024

// ---------------- scratch (device globals; no allocation allowed) ----------
__device__ __half g_xflowA[(size_t)N_FLOW * HH];   // ping (fp16 activations)
__device__ __half g_xflowB[(size_t)N_FLOW * HH];   // pong
__device__ __half g_trel  [(size_t)N_FLOW * HH];   // transformed flow (rel), fp16
__device__ __half g_th    [(size_t)N_HOST * HH];   // transformed host (h2f), fp16
__device__ float  g_xhostA[(size_t)N_HOST * HH];
__device__ float  g_xhostB[(size_t)N_HOST * HH];
__device__ float  g_aggh  [(size_t)N_HOST * HH];   // f2h aggregation into hosts

__device__ __half g_WFh[3][HH * 2 * HH]; // per layer fp16: [128][256]=[WoComb|Wr_rel]
__device__ float  g_Wf2hPad[HH * HH];    // pad(Wr0_f2h) 97->128 rows
__device__ float  g_biasF[3][HH];        // br_h2f + br_rel per layer
__device__ float  g_zeroBias[HH];        // zero-initialized device global

// CSR scratch (built once per launch, reused across layers)
__device__ int g_csr_rel[E_REL];
__device__ int g_csr_h2f[E_HF];
__device__ int g_csr_f2h[E_HF];
__device__ int g_off_rel[N_FLOW + 1];
__device__ int g_off_h2f[N_FLOW + 1];
__device__ int g_off_f2h[N_HOST + 1];
__device__ int g_cur_rel[N_FLOW];
__device__ int g_cur_h2f[N_FLOW];
__device__ int g_cur_f2h[N_HOST];
__device__ int g_cnt_rel[N_FLOW];
__device__ int g_cnt_h2f[N_FLOW];
__device__ int g_cnt_f2h[N_HOST];
__device__ int g_bsum[3][256];

__device__ unsigned g_poolEnc[GG * HH];

// ---------------- small helpers -------------------------------------------
__device__ __forceinline__ unsigned enc_f(float f) {
    unsigned u = __float_as_uint(f);
    return (u & 0x80000000u) ? ~u : (u | 0x80000000u);
}
__device__ __forceinline__ float dec_f(unsigned e) {
    return (e & 0x80000000u) ? __uint_as_float(e ^ 0x80000000u)
                             : __uint_as_float(~e);
}
__device__ __forceinline__ uint32_t smaddr(const void* p) {
    return (uint32_t)__cvta_generic_to_shared(p);
}
__device__ __forceinline__ void ldsm4(uint32_t& r0, uint32_t& r1,
                                      uint32_t& r2, uint32_t& r3, uint32_t a) {
    asm volatile("ldmatrix.sync.aligned.m8n8.x4.shared.b16 {%0,%1,%2,%3}, [%4];"
                 : "=r"(r0), "=r"(r1), "=r"(r2), "=r"(r3) : "r"(a));
}
__device__ __forceinline__ void ldsm4t(uint32_t& r0, uint32_t& r1,
                                       uint32_t& r2, uint32_t& r3, uint32_t a) {
    asm volatile("ldmatrix.sync.aligned.m8n8.x4.trans.shared.b16 {%0,%1,%2,%3}, [%4];"
                 : "=r"(r0), "=r"(r1), "=r"(r2), "=r"(r3) : "r"(a));
}
__device__ __forceinline__ void mma_f16(float4& d, const uint32_t* a,
                                        const uint32_t* b) {
    asm volatile(
        "mma.sync.aligned.m16n8k16.row.col.f32.f16.f16.f32 "
        "{%0,%1,%2,%3}, {%4,%5,%6,%7}, {%8,%9}, {%0,%1,%2,%3};"
        : "+f"(d.x), "+f"(d.y), "+f"(d.z), "+f"(d.w)
        : "r"(a[0]), "r"(a[1]), "r"(a[2]), "r"(a[3]), "r"(b[0]), "r"(b[1]));
}
__device__ __forceinline__ uint2 ldg_cs_u2(const void* p) {
    uint2 v;
    asm volatile("ld.global.cs.v2.u32 {%0,%1}, [%2];"
                 : "=r"(v.x), "=r"(v.y) : "l"(p));
    return v;
}
__device__ __forceinline__ void stg_cs_u2(void* p, uint2 v) {
    asm volatile("st.global.cs.v2.u32 [%0], {%1,%2};"
                 :: "l"(p), "r"(v.x), "r"(v.y) : "memory");
}

// ---------------- CSR construction -----------------------------------------
__global__ void hist_kernel(const int* __restrict__ dst, int* __restrict__ cnt,
                            int E) {
    int i = blockIdx.x * blockDim.x + threadIdx.x;
    if (i < E) atomicAdd(&cnt[__ldg(dst + i)], 1);
}

__global__ void scanA_kernel(const int* __restrict__ cnt, int* __restrict__ off,
                             int* __restrict__ bsum, int n) {
    __shared__ int sh[SCAN_BLK];
    int tx = threadIdx.x;
    int i = blockIdx.x * SCAN_BLK + tx;
    int v = (i < n) ? cnt[i] : 0;
    sh[tx] = v;
    __syncthreads();
    for (int d = 1; d < SCAN_BLK; d <<= 1) {
        int t = (tx >= d) ? sh[tx - d] : 0;
        __syncthreads();
        sh[tx] += t;
        __syncthreads();
    }
    if (i < n) off[i] = sh[tx] - v;
    if (tx == SCAN_BLK - 1) bsum[blockIdx.x] = sh[tx];
}

__global__ void scanB_kernel(int* __restrict__ bsum, int nb) {
    __shared__ int sh[256];
    int tx = threadIdx.x;
    int v = (tx < nb) ? bsum[tx] : 0;
    sh[tx] = v;
    __syncthreads();
    for (int d = 1; d < 256; d <<= 1) {
        int t = (tx >= d) ? sh[tx - d] : 0;
        __syncthreads();
        sh[tx] += t;
        __syncthreads();
    }
    if (tx < nb) bsum[tx] = sh[tx] - v;
}

__global__ void scanC_kernel(int* __restrict__ off, int* __restrict__ cur,
                             const int* __restrict__ bsum, int n, int E) {
    int i = blockIdx.x * SCAN_BLK + threadIdx.x;
    if (i < n) {
        int o = off[i] + bsum[blockIdx.x];
        off[i] = o;
        cur[i] = o;
    }
    if (i == 0) off[n] = E;
}

__global__ void fill_kernel(const int* __restrict__ src, const int* __restrict__ dst,
                            int* __restrict__ cur, int* __restrict__ csr, int E) {
    int i = blockIdx.x * blockDim.x + threadIdx.x;
    if (i < E) {
        int d = __ldg(dst + i);
        int p = atomicAdd(&cur[d], 1);
        csr[p] = __ldg(src + i);
    }
}

// ---------------- gathers ----------------------------------------------------
// fb traffic uses evict-first streaming hints; message reads keep L2 residency.
__global__ void gather_flow_kernel(const __half* __restrict__ trel,
                                   const __half* __restrict__ th,
                                   const int* __restrict__ off_rel,
                                   const int* __restrict__ csr_rel,
                                   const int* __restrict__ off_h2f,
                                   const int* __restrict__ csr_h2f,
                                   __half* __restrict__ fb) {
    int w = (blockIdx.x * blockDim.x + threadIdx.x) >> 5;
    int lane = threadIdx.x & 31;
    if (w >= N_FLOW) return;
    uint2* fp = (uint2*)(fb + (size_t)w * HH);
    uint2 fv = ldg_cs_u2(fp + lane);
    float2 a0 = __half22float2(*(__half2*)&fv.x);
    float2 a1 = __half22float2(*(__half2*)&fv.y);
    float4 acc = make_float4(a0.x, a0.y, a1.x, a1.y);
    int b = __ldg(off_rel + w), e = __ldg(off_rel + w + 1);
    for (int i = b; i < e; ++i) {
        int s = __ldg(csr_rel + i);
        uint2 v = ((const uint2*)(trel + (size_t)s * HH))[lane];
        float2 p0 = __half22float2(*(__half2*)&v.x);
        float2 p1 = __half22float2(*(__half2*)&v.y);
        acc.x += p0.x; acc.y += p0.y; acc.z += p1.x; acc.w += p1.y;
    }
    b = __ldg(off_h2f + w); e = __ldg(off_h2f + w + 1);
    for (int i = b; i < e; ++i) {
        int s = __ldg(csr_h2f + i);
        uint2 v = ((const uint2*)(th + (size_t)s * HH))[lane];
        float2 p0 = __half22float2(*(__half2*)&v.x);
        float2 p1 = __half22float2(*(__half2*)&v.y);
        acc.x += p0.x; acc.y += p0.y; acc.z += p1.x; acc.w += p1.y;
    }
    __half2 h0 = __floats2half2_rn(acc.x, acc.y);
    __half2 h1 = __floats2half2_rn(acc.z, acc.w);
    uint2 ov;
    ov.x = *(uint32_t*)&h0; ov.y = *(uint32_t*)&h1;
    stg_cs_u2(fp + lane, ov);
}

__global__ __launch_bounds__(256)
void gather_flow_pool_kernel(const __half* __restrict__ trel,
                             const __half* __restrict__ th,
                             const __half* __restrict__ fmain,
                             const int* __restrict__ off_rel,
                             const int* __restrict__ csr_rel,
                             const int* __restrict__ off_h2f,
                             const int* __restrict__ csr_h2f,
                             const int* __restrict__ batch,
                             unsigned* __restrict__ pe) {
    __shared__ float sm[8][HH];
    __shared__ int sg[8];
    int warp = threadIdx.x >> 5, lane = threadIdx.x & 31;
    int w = blockIdx.x * 8 + warp;
    float4 acc = make_float4(0.f, 0.f, 0.f, 0.f);
    int g = -1;
    if (w < N_FLOW) {
        g = __ldg(batch + w);
        uint2 fv = ldg_cs_u2((const uint2*)(fmain + (size_t)w * HH) + lane);
        float2 a0 = __half22float2(*(__half2*)&fv.x);
        float2 a1 = __half22float2(*(__half2*)&fv.y);
        acc = make_float4(a0.x, a0.y, a1.x, a1.y);
        int b = __ldg(off_rel + w), e = __ldg(off_rel + w + 1);
        for (int i = b; i < e; ++i) {
            int s = __ldg(csr_rel + i);
            uint2 v = ((const uint2*)(trel + (size_t)s * HH))[lane];
            float2 p0 = __half22float2(*(__half2*)&v.x);
            float2 p1 = __half22float2(*(__half2*)&v.y);
            acc.x += p0.x; acc.y += p0.y; acc.z += p1.x; acc.w += p1.y;
        }
        b = __ldg(off_h2f + w); e = __ldg(off_h2f + w + 1);
        for (int i = b; i < e; ++i) {
            int s = __ldg(csr_h2f + i);
            uint2 v = ((const uint2*)(th + (size_t)s * HH))[lane];
            float2 p0 = __half22float2(*(__half2*)&v.x);
            float2 p1 = __half22float2(*(__half2*)&v.y);
            acc.x += p0.x; acc.y += p0.y; acc.z += p1.x; acc.w += p1.y;
        }
    }
    if (lane == 0) sg[warp] = g;
    *(float4*)&sm[warp][lane * 4] = acc;
    __syncthreads();
    if (threadIdx.x < HH) {
        int c = threadIdx.x;
        int cur = sg[0];
        float m = -INFINITY;
#pragma unroll
        for (int r = 0; r < 8; ++r) {
            int gg = sg[r];
            if (gg != cur) {
                if (cur >= 0) atomicMax(&pe[cur * HH + c], enc_f(m));
                cur = gg; m = -INFINITY;
            }
            if (gg >= 0) m = fmaxf(m, sm[r][c]);
        }
        if (cur >= 0) atomicMax(&pe[cur * HH + c], enc_f(m));
    }
}

__global__ void gather_host_kernel(const __half* __restrict__ fa,
                                   const int* __restrict__ off,
                                   const int* __restrict__ csr,
                                   float* __restrict__ ah, int relu_in) {
    int w = (blockIdx.x * blockDim.x + threadIdx.x) >> 5;
    int lane = threadIdx.x & 31;
    if (w >= N_HOST) return;
    float4 acc = make_float4(0.f, 0.f, 0.f, 0.f);
    int b = __ldg(off + w), e = __ldg(off + w + 1);
    for (int i = b; i < e; ++i) {
        int s = __ldg(csr + i);
        uint2 v = ((const uint2*)(fa + (size_t)s * HH))[lane];
        float2 p0 = __half22float2(*(__half2*)&v.x);
        float2 p1 = __half22float2(*(__half2*)&v.y);
        if (relu_in) {
            p0.x = fmaxf(p0.x, 0.f); p0.y = fmaxf(p0.y, 0.f);
            p1.x = fmaxf(p1.x, 0.f); p1.y = fmaxf(p1.y, 0.f);
        }
        acc.x += p0.x; acc.y += p0.y; acc.z += p1.x; acc.w += p1.y;
    }
    ((float4*)(ah + (size_t)w * HH))[lane] = acc;
}

// ---------------- prep ------------------------------------------------------
__global__ void embed_kernel(const int* __restrict__ ids,
                             const float* __restrict__ table,
                             float* __restrict__ xh) {
    int i = blockIdx.x * blockDim.x + threadIdx.x;
    if (i >= N_HOST * HH) return;
    int row = i >> 7, c = i & 127;
    xh[i] = table[(size_t)__ldg(ids + row) * HH + c];
}

__global__ void pad_flow_kernel(const float* __restrict__ fx,
                                __half* __restrict__ xf) {
    int i = blockIdx.x * blockDim.x + threadIdx.x;
    if (i >= N_FLOW * HH) return;
    int row = i >> 7, c = i & 127;
    xf[i] = __float2half((c < FI) ? fx[(size_t)row * FI + c] : 0.f);
}

__global__ void prep_weights_kernel(const float* __restrict__ Wo0_h2f,
                                    const float* __restrict__ Wo0_rel,
                                    const float* __restrict__ Wr0_rel,
                                    const float* __restrict__ Wr0_f2h,
                                    const float* __restrict__ Wo,
                                    const float* __restrict__ Wr,
                                    const float* __restrict__ br0_h2f,
                                    const float* __restrict__ br0_rel,
                                    const float* __restrict__ br) {
    int k = blockIdx.x;
    int c = threadIdx.x;
    int idx = k * 256 + c;
    if (c < HH) {
        float v = (k < FI) ? (Wo0_h2f[k * HH + c] + Wo0_rel[k * HH + c]) : 0.f;
        g_WFh[0][idx] = __float2half(v);
        g_Wf2hPad[k * HH + c] = (k < FI) ? Wr0_f2h[k * HH + c] : 0.f;
    } else {
        int cc = c - HH;
        g_WFh[0][idx] = __float2half((k < FI) ? Wr0_rel[k * HH + cc] : 0.f);
    }
    for (int l = 0; l < 2; ++l) {
        float v;
        if (c < HH)
            v = Wo[((size_t)l * 3 + 0) * HH * HH + k * HH + c]
              + Wo[((size_t)l * 3 + 2) * HH * HH + k * HH + c];
        else
            v = Wr[((size_t)l * 3 + 2) * HH * HH + k * HH + (c - HH)];
        g_WFh[l + 1][idx] = __float2half(v);
    }
    if (k == 0 && c < HH) {
        g_biasF[0][c] = br0_h2f[c] + br0_rel[c];
        for (int l = 0; l < 2; ++l)
            g_biasF[l + 1][c] = br[(l * 3 + 0) * HH + c] + br[(l * 3 + 2) * HH + c];
        g_zeroBias[c] = 0.f;
    }
}

// ---------------- fp16 HMMA GEMM (flow path) --------------------------------
// 64x256 block tile, 256 thr = 8 warps (2M x 4N), warp tile 32x64, BK=16.
__global__ __launch_bounds__(256, 2)
void gemm_dual_h_kernel(const __half* __restrict__ A, const __half* __restrict__ W,
                        const float* __restrict__ bias,
                        __half* __restrict__ out_main, __half* __restrict__ out_aux,
                        int M, int relu_in) {
    const int BK = 16;
    __shared__ __half As[2][64][16];
    __shared__ __half Ws[2][BK][264];

    int tid  = threadIdx.x;
    int warp = tid >> 5, lane = tid & 31;
    int wm = warp >> 2, wn = warp & 3;          // 2 x 4 warp grid
    int tg = lane & 3, gp = lane >> 2;
    int row0 = blockIdx.x * 64;

    float4 acc[2][8];
#pragma unroll
    for (int i = 0; i < 2; ++i)
#pragma unroll
        for (int j = 0; j < 8; ++j) acc[i][j] = make_float4(0.f, 0.f, 0.f, 0.f);

    int a_r = tid >> 2, a_kq = tid & 3;         // 64 rows x 4 quarters
    int a_grow = row0 + a_r;
    uint2 aREG, wREG[4];
    const __half2 hz = __float2half2_rn(0.f);

    auto loadA = [&](int k0) {
        aREG = make_uint2(0u, 0u);
        if (a_grow < M)
            aREG = *(const uint2*)(A + (size_t)a_grow * HH + k0 + a_kq * 4);
        if (relu_in) {
            *(__half2*)&aREG.x = __hmax2(*(__half2*)&aREG.x, hz);
            *(__half2*)&aREG.y = __hmax2(*(__half2*)&aREG.y, hz);
        }
    };
    auto loadW = [&](int k0) {
#pragma unroll
        for (int i = 0; i < 4; ++i) {
            int idx = tid + i * 256;
            int kk = idx >> 6, cq = idx & 63;
            wREG[i] = *(const uint2*)(W + (size_t)(k0 + kk) * 256 + cq * 4);
        }
    };
    auto storeTile = [&](int buf) {
        *(uint2*)&As[buf][a_r][a_kq * 4] = aREG;
#pragma unroll
        for (int i = 0; i < 4; ++i) {
            int idx = tid + i * 256;
            int kk = idx >> 6, cq = idx & 63;
            *(uint2*)&Ws[buf][kk][cq * 4] = wREG[i];
        }
    };

    loadA(0); loadW(0);
    storeTile(0);
    __syncthreads();

    const int NITER = HH / BK;  // 8
    for (int iter = 0; iter < NITER; ++iter) {
        int cur = iter & 1;
        if (iter + 1 < NITER) {
            int k0 = (iter + 1) * BK;
            loadA(k0); loadW(k0);
        }
        uint32_t af[2][4];
#pragma unroll
        for (int mi = 0; mi < 2; ++mi) {
            int row = wm * 32 + mi * 16 + (lane & 15);
            int col = (lane >> 4) * 8;
            ldsm4(af[mi][0], af[mi][1], af[mi][2], af[mi][3],
                  smaddr(&As[cur][row][col]));
        }
        uint32_t bf[8][2];
#pragma unroll
        for (int pr = 0; pr < 4; ++pr) {
            int krow = lane & 15;
            int ncol = wn * 64 + pr * 16 + ((lane >> 4) * 8);
            uint32_t b0, b1, b2, b3;
            ldsm4t(b0, b1, b2, b3, smaddr(&Ws[cur][krow][ncol]));
            bf[pr * 2][0] = b0; bf[pr * 2][1] = b1;
            bf[pr * 2 + 1][0] = b2; bf[pr * 2 + 1][1] = b3;
        }
#pragma unroll
        for (int mi = 0; mi < 2; ++mi)
#pragma unroll
            for (int ni = 0; ni < 8; ++ni)
                mma_f16(acc[mi][ni], af[mi], bf[ni]);
        if (iter + 1 < NITER) storeTile(1 - cur);
        __syncthreads();
    }

#pragma unroll
    for (int ni = 0; ni < 8; ++ni) {
        int col = wn * 64 + ni * 8 + tg * 2;
        bool main_half = (col < HH);
        float b0 = 0.f, b1 = 0.f;
        if (main_half) { b0 = __ldg(bias + col); b1 = __ldg(bias + col + 1); }
        int oc = main_half ? col : (col - HH);
        __half* outp = main_half ? out_main : out_aux;
#pragma unroll
        for (int mi = 0; mi < 2; ++mi) {
            int r0 = row0 + wm * 32 + mi * 16 + gp;
            int r1 = r0 + 8;
            float4 d = acc[mi][ni];
            if (r0 < M)
                *(__half2*)(outp + (size_t)r0 * HH + oc) =
                    __floats2half2_rn(d.x + b0, d.y + b1);
            if (r1 < M)
                *(__half2*)(outp + (size_t)r1 * HH + oc) =
                    __floats2half2_rn(d.z + b0, d.w + b1);
        }
    }
}

// ---------------- fp32 GEMM (host path, small) ------------------------------
__global__ __launch_bounds__(256)
void gemm2_kernel(const float* __restrict__ A0, const float* __restrict__ W0,
                  const float* __restrict__ A1, const float* __restrict__ W1,
                  const float* __restrict__ bias, float* __restrict__ out,
                  __half* __restrict__ outh,
                  int M, int nsrc, int relu_mask) {
    const int BM = 128, BK = 16;
    __shared__ float As[BK][BM + 4];
    __shared__ float Ws[BK][128];
    int tid = threadIdx.x;
    int tx = tid & 15, ty = tid >> 4;
    int row0 = blockIdx.x * BM;
    float acc[8][8];
#pragma unroll
    for (int i = 0; i < 8; ++i)
#pragma unroll
        for (int j = 0; j < 8; ++j) acc[i][j] = 0.f;

    const float* Aarr[2] = {A0, A1};
    const float* Warr[2] = {W0, W1};

    for (int s = 0; s < nsrc; ++s) {
        const float* A = Aarr[s];
        const float* W = Warr[s];
        int rl = (relu_mask >> s) & 1;
        for (int k0 = 0; k0 < 128; k0 += BK) {
#pragma unroll
            for (int i = 0; i < 2; ++i) {
                int idx = tid + i * 256;
                int r = idx >> 2, kq = idx & 3;
                int grow = row0 + r;
                float4 v = make_float4(0.f, 0.f, 0.f, 0.f);
                if (grow < M)
                    v = *(const float4*)(A + (size_t)grow * 128 + k0 + kq * 4);
                if (rl) {
                    v.x = fmaxf(v.x, 0.f); v.y = fmaxf(v.y, 0.f);
                    v.z = fmaxf(v.z, 0.f); v.w = fmaxf(v.w, 0.f);
                }
                As[kq * 4 + 0][r] = v.x;
                As[kq * 4 + 1][r] = v.y;
                As[kq * 4 + 2][r] = v.z;
                As[kq * 4 + 3][r] = v.w;
            }
#pragma unroll
            for (int i = 0; i < 2; ++i) {
                int idx = tid + i * 256;
                int kk = idx >> 5, cq = idx & 31;
                *(float4*)&Ws[kk][cq * 4] =
                    *(const float4*)(W + (size_t)(k0 + kk) * 128 + cq * 4);
            }
            __syncthreads();
#pragma unroll
            for (int k = 0; k < BK; ++k) {
                float a[8], b[8];
#pragma unroll
                for (int i = 0; i < 8; i += 4)
                    *(float4*)&a[i] = *(const float4*)&As[k][ty * 8 + i];
#pragma unroll
                for (int j = 0; j < 8; j += 4)
                    *(float4*)&b[j] = *(const float4*)&Ws[k][tx * 8 + j];
#pragma unroll
                for (int i = 0; i < 8; ++i)
#pragma unroll
                    for (int j = 0; j < 8; ++j)
                        acc[i][j] = fmaf(a[i], b[j], acc[i][j]);
            }
            __syncthreads();
        }
    }
#pragma unroll
    for (int i = 0; i < 8; ++i) {
        int r = row0 + ty * 8 + i;
        if (r >= M) break;
        if (outh) {
#pragma unroll
            for (int j = 0; j < 8; j += 2) {
                float v0 = acc[i][j]   + __ldg(bias + tx * 8 + j);
                float v1 = acc[i][j+1] + __ldg(bias + tx * 8 + j + 1);
                *(__half2*)(outh + (size_t)r * 128 + tx * 8 + j) =
                    __floats2half2_rn(v0, v1);
            }
        } else {
#pragma unroll
            for (int j = 0; j < 8; ++j)
                out[(size_t)r * 128 + tx * 8 + j] = acc[i][j] + __ldg(bias + tx * 8 + j);
        }
    }
}

// ---------------- pooling + fused classifier --------------------------------
__global__ void pool_init_kernel(unsigned* __restrict__ pe) {
    int i = blockIdx.x * blockDim.x + threadIdx.x;
    if (i < GG * HH) pe[i] = 0x007FFFFFu;
}

__global__ __launch_bounds__(128)
void classifier_kernel(const unsigned* __restrict__ pe,
                       const float* __restrict__ Wc1, const float* __restrict__ bc1,
                       const float* __restrict__ Wc2, const float* __restrict__ bc2,
                       const float* __restrict__ Wc3, const float* __restrict__ bc3,
                       float* __restrict__ out) {
    __shared__ float sp[HH];
    __shared__ float sh1[64];
    __shared__ float sh2[HH];
    int g = blockIdx.x;
    int c = threadIdx.x;

    sp[c] = dec_f(pe[g * HH + c]);
    __syncthreads();

    if (c < 64) {
        float acc = bc1[c];
        for (int k = 0; k < HH; ++k)
            acc = fmaf(sp[k], __ldg(Wc1 + k * 64 + c), acc);
        sh1[c] = fmaxf(acc, 0.f);
    }
    __syncthreads();

    {
        float acc = bc2[c];
        for (int k = 0; k < 64; ++k)
            acc = fmaf(sh1[k], __ldg(Wc2 + k * HH + c), acc);
        sh2[c] = fmaxf(acc, 0.f);
    }
    __syncthreads();

    if (c < 10) {
        float acc = bc3[c];
        for (int k = 0; k < HH; ++k)
            acc = fmaf(sh2[k], __ldg(Wc3 + k * 10 + c), acc);
        out[g * 10 + c] = acc;
    }
}

// ---------------- host orchestration ---------------------------------------
static void build_csr(cudaStream_t st, const int* src, const int* dst, int E, int n,
                      int* cnt, int* off, int* cur, int* csr, int* bsum) {
    int nb = (n + SCAN_BLK - 1) / SCAN_BLK;
    cudaMemsetAsync(cnt, 0, (size_t)n * sizeof(int), st);
    hist_kernel<<<(E + 255) / 256, 256, 0, st>>>(dst, cnt, E);
    scanA_kernel<<<nb, SCAN_BLK, 0, st>>>(cnt, off, bsum, n);
    scanB_kernel<<<1, 256, 0, st>>>(bsum, nb);
    scanC_kernel<<<nb, SCAN_BLK, 0, st>>>(off, cur, bsum, n, E);
    fill_kernel<<<(E + 255) / 256, 256, 0, st>>>(src, dst, cur, csr, E);
}

extern "C" void kernel_launch(void* const* d_in, const int* in_sizes, int n_in,
                              void* d_out, int out_size) {
    const int*   host_ids  = (const int*)  d_in[0];
    const float* flow_x    = (const float*)d_in[1];
    const int*   h2f_src   = (const int*)  d_in[2];
    const int*   h2f_dst   = (const int*)  d_in[3];
    const int*   f2h_src   = (const int*)  d_in[4];
    const int*   f2h_dst   = (const int*)  d_in[5];
    const int*   rel_src   = (const int*)  d_in[6];
    const int*   rel_dst   = (const int*)  d_in[7];
    const int*   flow_batch= (const int*)  d_in[8];
    const float* host_embed= (const float*)d_in[9];
    const float* Wr0_h2f   = (const float*)d_in[10];
    const float* br0_h2f   = (const float*)d_in[11];
    const float* Wo0_h2f   = (const float*)d_in[12];
    const float* Wr0_f2h   = (const float*)d_in[13];
    const float* br0_f2h   = (const float*)d_in[14];
    const float* Wo0_f2h   = (const float*)d_in[15];
    const float* Wr0_rel   = (const float*)d_in[16];
    const float* br0_rel   = (const float*)d_in[17];
    const float* Wo0_rel   = (const float*)d_in[18];
    const float* Wr        = (const float*)d_in[19];  // [2,3,128,128]
    const float* br        = (const float*)d_in[20];  // [2,3,128]
    const float* Wo        = (const float*)d_in[21];  // [2,3,128,128]
    const float* Wc1       = (const float*)d_in[22];
    const float* bc1       = (const float*)d_in[23];
    const float* Wc2       = (const float*)d_in[24];
    const float* bc2       = (const float*)d_in[25];
    const float* Wc3       = (const float*)d_in[26];
    const float* bc3       = (const float*)d_in[27];
    float* out = (float*)d_out;

    __half *xfA, *xfB, *trel, *th, *WFh;
    float *xhA, *xhB, *ah;
    float *Wf2hPad, *biasF, *zeroBias;
    unsigned* poolEnc;
    int *csr_rel, *csr_h2f, *csr_f2h;
    int *off_rel, *off_h2f, *off_f2h;
    int *cur_rel, *cur_h2f, *cur_f2h;
    int *cnt_rel, *cnt_h2f, *cnt_f2h, *bsum;
    cudaGetSymbolAddress((void**)&xfA, g_xflowA);
    cudaGetSymbolAddress((void**)&xfB, g_xflowB);
    cudaGetSymbolAddress((void**)&trel, g_trel);
    cudaGetSymbolAddress((void**)&th,  g_th);
    cudaGetSymbolAddress((void**)&xhA, g_xhostA);
    cudaGetSymbolAddress((void**)&xhB, g_xhostB);
    cudaGetSymbolAddress((void**)&ah,  g_aggh);
    cudaGetSymbolAddress((void**)&WFh, g_WFh);
    cudaGetSymbolAddress((void**)&Wf2hPad, g_Wf2hPad);
    cudaGetSymbolAddress((void**)&biasF,   g_biasF);
    cudaGetSymbolAddress((void**)&zeroBias, g_zeroBias);
    cudaGetSymbolAddress((void**)&poolEnc, g_poolEnc);
    cudaGetSymbolAddress((void**)&csr_rel, g_csr_rel);
    cudaGetSymbolAddress((void**)&csr_h2f, g_csr_h2f);
    cudaGetSymbolAddress((void**)&csr_f2h, g_csr_f2h);
    cudaGetSymbolAddress((void**)&off_rel, g_off_rel);
    cudaGetSymbolAddress((void**)&off_h2f, g_off_h2f);
    cudaGetSymbolAddress((void**)&off_f2h, g_off_f2h);
    cudaGetSymbolAddress((void**)&cur_rel, g_cur_rel);
    cudaGetSymbolAddress((void**)&cur_h2f, g_cur_h2f);
    cudaGetSymbolAddress((void**)&cur_f2h, g_cur_f2h);
    cudaGetSymbolAddress((void**)&cnt_rel, g_cnt_rel);
    cudaGetSymbolAddress((void**)&cnt_h2f, g_cnt_h2f);
    cudaGetSymbolAddress((void**)&cnt_f2h, g_cnt_f2h);
    cudaGetSymbolAddress((void**)&bsum, g_bsum);

    static cudaStream_t sB = nullptr;
    static cudaEvent_t evFork = nullptr, evPrep = nullptr, evCsrB = nullptr,
                       evTh = nullptr, evFlow = nullptr, evHG = nullptr;
    if (!sB) {
        cudaStreamCreateWithFlags(&sB, cudaStreamNonBlocking);
        cudaEventCreateWithFlags(&evFork, cudaEventDisableTiming);
        cudaEventCreateWithFlags(&evPrep, cudaEventDisableTiming);
        cudaEventCreateWithFlags(&evCsrB, cudaEventDisableTiming);
        cudaEventCreateWithFlags(&evTh,   cudaEventDisableTiming);
        cudaEventCreateWithFlags(&evFlow, cudaEventDisableTiming);
        cudaEventCreateWithFlags(&evHG,   cudaEventDisableTiming);
    }
    cudaStream_t s0 = 0;

    int flowBlocks = (N_FLOW + 63) / 64;
    int hostBlocks = (N_HOST + 127) / 128;

    cudaEventRecord(evFork, s0);
    cudaStreamWaitEvent(sB, evFork, 0);

    // s0 prologue: weights + padded fp16 flow features, then GEMM L0
    prep_weights_kernel<<<HH, 256, 0, s0>>>(Wo0_h2f, Wo0_rel, Wr0_rel, Wr0_f2h,
                                            Wo, Wr, br0_h2f, br0_rel, br);
    pad_flow_kernel<<<(N_FLOW * HH + 255) / 256, 256, 0, s0>>>(flow_x, xfA);
    cudaEventRecord(evPrep, s0);

    // sB prologue: embed + pool init + th(L0) + CSR builds + host chain L0
    embed_kernel<<<(N_HOST * HH + 255) / 256, 256, 0, sB>>>(host_ids, host_embed, xhA);
    pool_init_kernel<<<(GG * HH + 255) / 256, 256, 0, sB>>>(poolEnc);
    gemm2_kernel<<<hostBlocks, 256, 0, sB>>>(xhA, Wr0_h2f, nullptr, nullptr,
                                             zeroBias, nullptr, th, N_HOST, 1, 0);
    cudaEventRecord(evTh, sB);
    build_csr(sB, rel_src, rel_dst, E_REL, N_FLOW, cnt_rel, off_rel, cur_rel, csr_rel, bsum + 0 * 256);
    build_csr(sB, h2f_src, h2f_dst, E_HF,  N_FLOW, cnt_h2f, off_h2f, cur_h2f, csr_h2f, bsum + 1 * 256);
    cudaEventRecord(evCsrB, sB);
    build_csr(sB, f2h_src, f2h_dst, E_HF,  N_HOST, cnt_f2h, off_f2h, cur_f2h, csr_f2h, bsum + 2 * 256);
    cudaStreamWaitEvent(sB, evPrep, 0);
    gather_host_kernel<<<(N_HOST * 32 + 255) / 256, 256, 0, sB>>>(
        xfA, off_f2h, csr_f2h, ah, 0);
    cudaEventRecord(evHG, sB);
    gemm2_kernel<<<hostBlocks, 256, 0, sB>>>(ah, Wf2hPad, xhA, Wo0_f2h, br0_f2h,
                                             xhB, nullptr, N_HOST, 2, 0);

    // ---- layer 0 flow (s0) ----
    gemm_dual_h_kernel<<<flowBlocks, 256, 0, s0>>>(xfA, WFh, biasF, xfB, trel, N_FLOW, 0);
    cudaStreamWaitEvent(s0, evTh, 0);
    cudaStreamWaitEvent(s0, evCsrB, 0);
    gather_flow_kernel<<<(N_FLOW * 32 + 255) / 256, 256, 0, s0>>>(
        trel, th, off_rel, csr_rel, off_h2f, csr_h2f, xfB);
    cudaEventRecord(evFlow, s0);

    // ---- layer 1 ----
    {
        const __half* WF1 = WFh + (size_t)1 * HH * 2 * HH;
        const float* bF1 = biasF + (size_t)1 * HH;
        const float* WrH2F = Wr + (size_t)(0 * 3 + 0) * HH * HH;
        const float* WrF2H = Wr + (size_t)(0 * 3 + 1) * HH * HH;
        const float* WoF2H = Wo + (size_t)(0 * 3 + 1) * HH * HH;
        const float* bH    = br + (0 * 3 + 1) * HH;

        cudaStreamWaitEvent(s0, evHG, 0);  // gather_host L0 read xfA
        gemm_dual_h_kernel<<<flowBlocks, 256, 0, s0>>>(xfB, WF1, bF1, xfA, trel, N_FLOW, 1);

        cudaStreamWaitEvent(sB, evFlow, 0);
        gemm2_kernel<<<hostBlocks, 256, 0, sB>>>(xhB, WrH2F, nullptr, nullptr,
                                                 zeroBias, nullptr, th, N_HOST, 1, 1);
        cudaEventRecord(evTh, sB);
        gather_host_kernel<<<(N_HOST * 32 + 255) / 256, 256, 0, sB>>>(
            xfB, off_f2h, csr_f2h, ah, 1);
        cudaEventRecord(evHG, sB);
        gemm2_kernel<<<hostBlocks, 256, 0, sB>>>(ah, WrF2H, xhB, WoF2H, bH,
                                                 xhA, nullptr, N_HOST, 2, 2);

        cudaStreamWaitEvent(s0, evTh, 0);
        gather_flow_kernel<<<(N_FLOW * 32 + 255) / 256, 256, 0, s0>>>(
            trel, th, off_rel, csr_rel, off_h2f, csr_h2f, xfA);
        cudaEventRecord(evFlow, s0);
    }

    // ---- layer 2 (flow only; fused gather+pool) ----
    {
        const __half* WF2 = WFh + (size_t)2 * HH * 2 * HH;
        const float* bF2 = biasF + (size_t)2 * HH;
        const float* WrH2F = Wr + (size_t)(1 * 3 + 0) * HH * HH;

        cudaStreamWaitEvent(s0, evHG, 0);  // gather_host L1 read xfB
        gemm_dual_h_kernel<<<flowBlocks, 256, 0, s0>>>(xfA, WF2, bF2, xfB, trel, N_FLOW, 1);

        cudaStreamWaitEvent(sB, evFlow, 0);
        gemm2_kernel<<<hostBlocks, 256, 0, sB>>>(xhA, WrH2F, nullptr, nullptr,
                                                 zeroBias, nullptr, th, N_HOST, 1, 1);
        cudaEventRecord(evTh, sB);

        cudaStreamWaitEvent(s0, evTh, 0);
        gather_flow_pool_kernel<<<(N_FLOW + 7) / 8, 256, 0, s0>>>(
            trel, th, xfB, off_rel, csr_rel, off_h2f, csr_h2f, flow_batch, poolEnc);
    }

    // fused classifier tail (one launch)
    classifier_kernel<<<GG, 128, 0, s0>>>(poolEnc, Wc1, bc1, Wc2, bc2, Wc3, bc3, out);
}